// round 14
// baseline (speedup 1.0000x reference)
#include <cuda_runtime.h>
#include <cuda_bf16.h>
#include <cuda_fp16.h>
#include <cstdint>

// Problem constants
#define BB    4
#define SS    2048
#define DD    256
#define HH    8
#define DHH   32
#define DFF   512
#define NTOK  (BB*SS)          // 8192
#define EPS   1e-5f
// softmax scale * log2(e), folded into Q at QKV epilogue
#define ATT_SC2 0.25503540f
#define KSPLIT 4
#define KSEG   (SS/KSPLIT)     // 512

// smem row pitch in halves (80B): conflict-free + 16B-aligned rows for ldmatrix
#define PITCH 40

// ---------------------------------------------------------------------------
// Scratch (device globals; no allocations allowed)
// ---------------------------------------------------------------------------
__device__ __nv_bfloat16 g_yb [NTOK * DD];        // LN output (bf16)
__device__ float         g_x1 [NTOK * DD];        // residual after attention
__device__ __nv_bfloat16 g_hb [NTOK * DFF];       // FFN hidden (bf16)
__device__ __nv_bfloat16 g_qb[BB*HH * SS * DHH];  // Q bf16 (pre-scaled) [bh][s][32]
__device__ __nv_bfloat16 g_kb[BB*HH * SS * DHH];  // K bf16
__device__ __half        g_vh[BB*HH * SS * DHH];  // V fp16
__device__ __nv_bfloat16 g_wqkvb[3*DD * DD];      // bf16 weights
__device__ __nv_bfloat16 g_wprojb[DD * DD];
__device__ __nv_bfloat16 g_w1b[DFF * DD];
__device__ __nv_bfloat16 g_w2b[DD * DFF];
__device__ float g_po[KSPLIT * NTOK * DD];        // split-K partial O (fp32)
__device__ float g_pl[KSPLIT * NTOK * HH];        // split-K partial l

__device__ __forceinline__ uint32_t packbf(float lo, float hi) {
    __nv_bfloat162 t = __floats2bfloat162_rn(lo, hi);
    return *reinterpret_cast<uint32_t*>(&t);
}
// pack 2 fp32 exponent args -> f16x2, then 2^x on both halves (1 MUFU op)
__device__ __forceinline__ uint32_t exp2h2(float lo, float hi) {
    uint32_t d;
    asm("cvt.rn.f16x2.f32 %0, %1, %2;" : "=r"(d) : "f"(hi), "f"(lo));
    asm("ex2.approx.f16x2 %0, %0;" : "+r"(d));
    return d;
}
__device__ __forceinline__ void cpa16(uint32_t dst, const void* src) {
    asm volatile("cp.async.cg.shared.global [%0], [%1], 16;" :: "r"(dst), "l"(src));
}

// ---------------------------------------------------------------------------
// One-shot fp32 -> bf16 conversion of ALL weight matrices.
// ---------------------------------------------------------------------------
__global__ void f2bf_all(const float* __restrict__ s0, const float* __restrict__ s1,
                         const float* __restrict__ s2, const float* __restrict__ s3,
                         __nv_bfloat16* __restrict__ d0, __nv_bfloat16* __restrict__ d1,
                         __nv_bfloat16* __restrict__ d2, __nv_bfloat16* __restrict__ d3) {
    int i = blockIdx.x * 256 + threadIdx.x;     // 0..32767
    int idx = i * 16;
    const float* src; __nv_bfloat16* dst; int off;
    if (idx < 196608)      { src = s0; dst = d0; off = idx; }
    else if (idx < 262144) { src = s1; dst = d1; off = idx - 196608; }
    else if (idx < 393216) { src = s2; dst = d2; off = idx - 262144; }
    else                   { src = s3; dst = d3; off = idx - 393216; }
    float4 v0 = *(const float4*)(src + off);
    float4 v1 = *(const float4*)(src + off + 4);
    float4 v2 = *(const float4*)(src + off + 8);
    float4 v3 = *(const float4*)(src + off + 12);
    uint4 o0, o1;
    o0.x = packbf(v0.x, v0.y); o0.y = packbf(v0.z, v0.w);
    o0.z = packbf(v1.x, v1.y); o0.w = packbf(v1.z, v1.w);
    o1.x = packbf(v2.x, v2.y); o1.y = packbf(v2.z, v2.w);
    o1.z = packbf(v3.x, v3.y); o1.w = packbf(v3.z, v3.w);
    *(uint4*)(dst + off)     = o0;
    *(uint4*)(dst + off + 8) = o1;
}

// ---------------------------------------------------------------------------
// LayerNorm -> bf16: one WARP per row (8 rows per 256-thread block)
// ---------------------------------------------------------------------------
__device__ __forceinline__ float warp_sum(float v) {
    #pragma unroll
    for (int o = 16; o > 0; o >>= 1) v += __shfl_xor_sync(0xffffffffu, v, o);
    return v;
}

__global__ __launch_bounds__(256) void ln_kernel(const float* __restrict__ x,
                                                 const float* __restrict__ g,
                                                 const float* __restrict__ b,
                                                 __nv_bfloat16* __restrict__ y) {
    int row  = blockIdx.x * 8 + (threadIdx.x >> 5);
    int lane = threadIdx.x & 31;
    const float* xr = x + (size_t)row * DD + lane * 8;

    float4 v0 = *(const float4*)(xr);
    float4 v1 = *(const float4*)(xr + 4);
    float d[8] = {v0.x, v0.y, v0.z, v0.w, v1.x, v1.y, v1.z, v1.w};

    float s = d[0]+d[1]+d[2]+d[3]+d[4]+d[5]+d[6]+d[7];
    float mean = warp_sum(s) * (1.0f / DD);

    float ss = 0.f;
    #pragma unroll
    for (int j = 0; j < 8; j++) { d[j] -= mean; ss += d[j] * d[j]; }
    float var = warp_sum(ss) * (1.0f / DD);
    float r = rsqrtf(var + EPS);

    float4 g0 = *(const float4*)(g + lane * 8);
    float4 g1 = *(const float4*)(g + lane * 8 + 4);
    float4 b0 = *(const float4*)(b + lane * 8);
    float4 b1 = *(const float4*)(b + lane * 8 + 4);
    float gg[8] = {g0.x, g0.y, g0.z, g0.w, g1.x, g1.y, g1.z, g1.w};
    float bb2[8] = {b0.x, b0.y, b0.z, b0.w, b1.x, b1.y, b1.z, b1.w};

    float o[8];
    #pragma unroll
    for (int j = 0; j < 8; j++) o[j] = d[j] * r * gg[j] + bb2[j];

    uint4 pk;
    pk.x = packbf(o[0], o[1]);
    pk.y = packbf(o[2], o[3]);
    pk.z = packbf(o[4], o[5]);
    pk.w = packbf(o[6], o[7]);
    *(uint4*)&y[(size_t)row * DD + lane * 8] = pk;
}

// ---------------------------------------------------------------------------
// mma helpers
// ---------------------------------------------------------------------------
__device__ __forceinline__ void ldmx4(uint32_t& r0, uint32_t& r1,
                                      uint32_t& r2, uint32_t& r3, uint32_t a) {
    asm volatile("ldmatrix.sync.aligned.m8n8.x4.shared.b16 {%0,%1,%2,%3}, [%4];\n"
                 : "=r"(r0), "=r"(r1), "=r"(r2), "=r"(r3) : "r"(a));
}
__device__ __forceinline__ void ldmx4t(uint32_t& r0, uint32_t& r1,
                                       uint32_t& r2, uint32_t& r3, uint32_t a) {
    asm volatile("ldmatrix.sync.aligned.m8n8.x4.trans.shared.b16 {%0,%1,%2,%3}, [%4];\n"
                 : "=r"(r0), "=r"(r1), "=r"(r2), "=r"(r3) : "r"(a));
}
__device__ __forceinline__ void mma16816(float* c, const uint32_t* a, const uint32_t* b) {
    asm volatile("mma.sync.aligned.m16n8k16.row.col.f32.bf16.bf16.f32 "
                 "{%0,%1,%2,%3}, {%4,%5,%6,%7}, {%8,%9}, {%0,%1,%2,%3};\n"
                 : "+f"(c[0]), "+f"(c[1]), "+f"(c[2]), "+f"(c[3])
                 : "r"(a[0]), "r"(a[1]), "r"(a[2]), "r"(a[3]),
                   "r"(b[0]), "r"(b[1]));
}
__device__ __forceinline__ void mma16816h(float* c, const uint32_t* a, const uint32_t* b) {
    asm volatile("mma.sync.aligned.m16n8k16.row.col.f32.f16.f16.f32 "
                 "{%0,%1,%2,%3}, {%4,%5,%6,%7}, {%8,%9}, {%0,%1,%2,%3};\n"
                 : "+f"(c[0]), "+f"(c[1]), "+f"(c[2]), "+f"(c[3])
                 : "r"(a[0]), "r"(a[1]), "r"(a[2]), "r"(a[3]),
                   "r"(b[0]), "r"(b[1]));
}

// 4-way split-K combine of one 128-row x 16-col slab -> bf16 into As tile
__device__ __forceinline__ void combine_tile(const float* __restrict__ po,
                                             const float* __restrict__ pl,
                                             int n4, int ac4, int kt,
                                             __nv_bfloat16* __restrict__ dst,
                                             int ar4) {
    const float* p0 = po + (size_t)n4 * DD + kt * 32 + ac4;
    float4 s[4];
    #pragma unroll
    for (int i = 0; i < 4; i++) s[i] = *(const float4*)(p0 + i * 4);
    float l = pl[(size_t)n4 * HH + kt];
    #pragma unroll
    for (int z = 1; z < KSPLIT; z++) {
        const float* pz = p0 + (size_t)z * NTOK * DD;
        #pragma unroll
        for (int i = 0; i < 4; i++) {
            float4 v = *(const float4*)(pz + i * 4);
            s[i].x += v.x; s[i].y += v.y; s[i].z += v.z; s[i].w += v.w;
        }
        l += pl[(size_t)z * NTOK * HH + (size_t)n4 * HH + kt];
    }
    float inv = 1.0f / l;
    uint4 o0, o1;
    o0.x = packbf(s[0].x * inv, s[0].y * inv);
    o0.y = packbf(s[0].z * inv, s[0].w * inv);
    o0.z = packbf(s[1].x * inv, s[1].y * inv);
    o0.w = packbf(s[1].z * inv, s[1].w * inv);
    o1.x = packbf(s[2].x * inv, s[2].y * inv);
    o1.y = packbf(s[2].z * inv, s[2].w * inv);
    o1.z = packbf(s[3].x * inv, s[3].y * inv);
    o1.w = packbf(s[3].z * inv, s[3].w * inv);
    *(uint4*)&dst[ar4 * PITCH + ac4]     = o0;
    *(uint4*)&dst[ar4 * PITCH + ac4 + 8] = o1;
}

// ---------------------------------------------------------------------------
// bf16 tensor-core NT GEMM (R11 shape): 128x64 tile, BK=32, 256 threads,
// 2-stage cp.async pipeline. Warp tile 32x32.
// MODE 1: fp32 out + residual
// MODE 2: silu -> bf16 out
// MODE 3: qkv scatter (Q bf16 pre-scaled by ATT_SC2, K bf16, V fp16)
// MODE 4: like 1, but A = split-K partial O (KSPLIT x fp32) combined inline
// ---------------------------------------------------------------------------
template<int MODE>
__global__ __launch_bounds__(256) void gemm_bf(
        const __nv_bfloat16* __restrict__ A,
        const __nv_bfloat16* __restrict__ W,
        const float* __restrict__ bias,
        const float* __restrict__ res,
        float* __restrict__ C,
        __nv_bfloat16* __restrict__ Ob,
        __nv_bfloat16* __restrict__ Kb,
        __half* __restrict__ Vh,
        const float* __restrict__ pl,
        int M, int K) {
    __shared__ __nv_bfloat16 As[2][128 * PITCH];
    __shared__ __nv_bfloat16 Bs[2][64 * PITCH];

    int t = threadIdx.x, w = t >> 5, lane = t & 31;
    int wm = w >> 1;
    int wn = w & 1;
    int row0 = blockIdx.y * 128;
    int col0 = blockIdx.x * 64;

    uint32_t ab_[2] = { (uint32_t)__cvta_generic_to_shared(As[0]),
                        (uint32_t)__cvta_generic_to_shared(As[1]) };
    uint32_t bb_[2] = { (uint32_t)__cvta_generic_to_shared(Bs[0]),
                        (uint32_t)__cvta_generic_to_shared(Bs[1]) };

    // cp.async indices: A 2 per thread, B 1 per thread
    int ar = t >> 1, ac = (t & 1) * 2;
    int br = t >> 2, bc = t & 3;
    uint32_t soA0 = (uint32_t)(ar * PITCH + ac * 8) * 2;
    uint32_t soA1 = (uint32_t)(ar * PITCH + (ac + 1) * 8) * 2;
    uint32_t soB  = (uint32_t)(br * PITCH + bc * 8) * 2;
    const __nv_bfloat16* asrc = A + (size_t)(row0 + ar) * K;
    const __nv_bfloat16* bsrc = W + (size_t)(col0 + br) * K;

    // MODE 4: inline split-K combine indices (2 threads per row)
    int ar4 = t >> 1, ac4 = (t & 1) * 16;
    int n4  = row0 + ar4;
    const float* po = reinterpret_cast<const float*>(A);

    float c[2][4][4];
    #pragma unroll
    for (int i = 0; i < 2; i++)
        #pragma unroll
        for (int j = 0; j < 4; j++)
            #pragma unroll
            for (int k = 0; k < 4; k++) c[i][j][k] = 0.f;

    // prologue
    cpa16(bb_[0] + soB, bsrc + bc * 8);
    if (MODE != 4) {
        cpa16(ab_[0] + soA0, asrc + ac * 8);
        cpa16(ab_[0] + soA1, asrc + (ac + 1) * 8);
    }
    asm volatile("cp.async.commit_group;");

    if (MODE == 4) {
        combine_tile(po, pl, n4, ac4, 0, As[0], ar4);
    }

    int NK = K >> 5;
    for (int it = 0; it < NK; it++) {
        int cur = it & 1;
        int nb = cur ^ 1;
        if (it + 1 < NK) {
            int k0 = (it + 1) * 32;
            cpa16(bb_[nb] + soB, bsrc + k0 + bc * 8);
            if (MODE != 4) {
                cpa16(ab_[nb] + soA0, asrc + k0 + ac * 8);
                cpa16(ab_[nb] + soA1, asrc + k0 + (ac + 1) * 8);
            }
            asm volatile("cp.async.commit_group;");
            asm volatile("cp.async.wait_group 1;");
        } else {
            asm volatile("cp.async.wait_group 0;");
        }
        __syncthreads();

        uint32_t abase = ab_[cur], bbase = bb_[cur];
        uint32_t bf[2][2][4];
        #pragma unroll
        for (int nt = 0; nt < 2; nt++) {
            int nrow = wn * 32 + nt * 16 + (lane & 7) + ((lane >> 4) << 3);
            #pragma unroll
            for (int ks = 0; ks < 2; ks++) {
                uint32_t ad = bbase + (uint32_t)(nrow * PITCH + ks * 16 + (lane & 8)) * 2;
                ldmx4(bf[nt][ks][0], bf[nt][ks][1], bf[nt][ks][2], bf[nt][ks][3], ad);
            }
        }
        #pragma unroll
        for (int mt = 0; mt < 2; mt++) {
            int arow = wm * 32 + mt * 16 + (lane & 15);
            #pragma unroll
            for (int ks = 0; ks < 2; ks++) {
                uint32_t af[4];
                uint32_t ad = abase + (uint32_t)(arow * PITCH + ks * 16 + ((lane >> 4) << 3)) * 2;
                ldmx4(af[0], af[1], af[2], af[3], ad);
                #pragma unroll
                for (int nt = 0; nt < 2; nt++) {
                    mma16816(c[mt][2 * nt],     af, &bf[nt][ks][0]);
                    mma16816(c[mt][2 * nt + 1], af, &bf[nt][ks][2]);
                }
            }
        }

        // MODE 4: combine + store next A tile into the other buffer
        if (MODE == 4 && it + 1 < NK) {
            combine_tile(po, pl, n4, ac4, it + 1, As[nb], ar4);
        }
        __syncthreads();
    }

    #pragma unroll
    for (int mt = 0; mt < 2; mt++) {
        #pragma unroll
        for (int half = 0; half < 2; half++) {
            int row = row0 + wm * 32 + mt * 16 + (lane >> 2) + half * 8;
            #pragma unroll
            for (int n8 = 0; n8 < 4; n8++) {
                int col = col0 + wn * 32 + n8 * 8 + 2 * (lane & 3);
                float v0 = c[mt][n8][2 * half]     + bias[col];
                float v1 = c[mt][n8][2 * half + 1] + bias[col + 1];
                if (MODE == 1 || MODE == 4) {
                    const float2 r2 = *(const float2*)&res[(size_t)row * M + col];
                    float2 o; o.x = v0 + r2.x; o.y = v1 + r2.y;
                    *(float2*)&C[(size_t)row * M + col] = o;
                } else if (MODE == 2) {
                    v0 = v0 * (1.0f / (1.0f + __expf(-v0)));
                    v1 = v1 * (1.0f / (1.0f + __expf(-v1)));
                    *(__nv_bfloat162*)&Ob[(size_t)row * M + col] =
                        __floats2bfloat162_rn(v0, v1);
                } else {
                    int seg = col >> 8, rem = col & 255;
                    int h = rem >> 5, d = rem & 31;
                    int b = row >> 11, s = row & 2047;
                    size_t di = ((size_t)(b * HH + h) * SS + s) * DHH + d;
                    if (seg == 0) {
                        *(__nv_bfloat162*)&Ob[di] =
                            __floats2bfloat162_rn(v0 * ATT_SC2, v1 * ATT_SC2);
                    } else if (seg == 1) {
                        *(__nv_bfloat162*)&Kb[di] = __floats2bfloat162_rn(v0, v1);
                    } else {
                        *(__half2*)&Vh[di] = __floats2half2_rn(v0, v1);
                    }
                }
            }
        }
    }
}

// ---------------------------------------------------------------------------
// Split-K tensor-core flash attention.
// S-mma: bf16 (Q pre-scaled). P = ex2.f16x2 of scores. PV-mma: fp16.
// grid (BH=32, S/128=16, KSPLIT=4), block 128 (4 warps; warp owns 32 q rows).
// Each block handles KSEG=512 keys; writes UNNORMALIZED partial O + l.
// ---------------------------------------------------------------------------
__global__ __launch_bounds__(128) void attn_mma(const __nv_bfloat16* __restrict__ Qb,
                                                const __nv_bfloat16* __restrict__ Kb,
                                                const __half* __restrict__ Vh,
                                                float* __restrict__ po,
                                                float* __restrict__ pl) {
    __shared__ __nv_bfloat16 Qs[128 * PITCH];
    __shared__ __nv_bfloat16 Ks[2][64 * PITCH];
    __shared__ __half        Vs[2][64 * PITCH];

    int bh = blockIdx.x;
    int qt = blockIdx.y;
    int z  = blockIdx.z;
    int t = threadIdx.x, w = t >> 5, lane = t & 31;

    const __nv_bfloat16* qsrc = Qb + ((size_t)bh * SS + qt * 128) * DHH;
    const __nv_bfloat16* ksrc = Kb + ((size_t)bh * SS + z * KSEG) * DHH;
    const __half*        vsrc = Vh + ((size_t)bh * SS + z * KSEG) * DHH;

    uint32_t qbase = (uint32_t)__cvta_generic_to_shared(Qs);
    uint32_t kb_[2] = { (uint32_t)__cvta_generic_to_shared(Ks[0]),
                        (uint32_t)__cvta_generic_to_shared(Ks[1]) };
    uint32_t vb_[2] = { (uint32_t)__cvta_generic_to_shared(Vs[0]),
                        (uint32_t)__cvta_generic_to_shared(Vs[1]) };

    #pragma unroll
    for (int i = t; i < 512; i += 128) {
        int r = i >> 2, s = i & 3;
        *(uint4*)&Qs[r * PITCH + s * 8] = *(const uint4*)&qsrc[r * 32 + s * 8];
    }

    int lr = t >> 2, ls = t & 3;
    uint32_t so0 = (uint32_t)(lr * PITCH + ls * 8) * 2;
    uint32_t so1 = (uint32_t)((lr + 32) * PITCH + ls * 8) * 2;

    cpa16(kb_[0] + so0, &ksrc[lr * 32 + ls * 8]);
    cpa16(kb_[0] + so1, &ksrc[(lr + 32) * 32 + ls * 8]);
    cpa16(vb_[0] + so0, &vsrc[lr * 32 + ls * 8]);
    cpa16(vb_[0] + so1, &vsrc[(lr + 32) * 32 + ls * 8]);
    asm volatile("cp.async.commit_group;");

    __syncthreads();   // Q ready

    uint32_t qa[2][2][4];
    #pragma unroll
    for (int mt = 0; mt < 2; mt++) {
        int row = w * 32 + mt * 16 + (lane & 15);
        #pragma unroll
        for (int ks = 0; ks < 2; ks++) {
            uint32_t a = qbase + (uint32_t)(row * PITCH + ks * 16 + ((lane >> 4) << 3)) * 2;
            ldmx4(qa[mt][ks][0], qa[mt][ks][1], qa[mt][ks][2], qa[mt][ks][3], a);
        }
    }

    float O[2][4][4];
    #pragma unroll
    for (int mt = 0; mt < 2; mt++)
        #pragma unroll
        for (int i = 0; i < 4; i++)
            #pragma unroll
            for (int j = 0; j < 4; j++) O[mt][i][j] = 0.f;
    float Oext[2][4] = {{0.f,0.f,0.f,0.f},{0.f,0.f,0.f,0.f}};
    const uint32_t onesh[2] = {0x3C003C00u, 0x3C003C00u};   // f16 1.0 x2

    const int NIT = KSEG / 64;   // 8
    for (int it = 0; it < NIT; it++) {
        int cur = it & 1;
        if (it + 1 < NIT) {
            int koff = (it + 1) * 64;
            int nb = cur ^ 1;
            cpa16(kb_[nb] + so0, &ksrc[(koff + lr) * 32 + ls * 8]);
            cpa16(kb_[nb] + so1, &ksrc[(koff + lr + 32) * 32 + ls * 8]);
            cpa16(vb_[nb] + so0, &vsrc[(koff + lr) * 32 + ls * 8]);
            cpa16(vb_[nb] + so1, &vsrc[(koff + lr + 32) * 32 + ls * 8]);
            asm volatile("cp.async.commit_group;");
            asm volatile("cp.async.wait_group 1;");
        } else {
            asm volatile("cp.async.wait_group 0;");
        }
        __syncthreads();

        uint32_t kba = kb_[cur], vba = vb_[cur];
        #pragma unroll
        for (int j = 0; j < 4; j++) {            // 16-key slabs
            uint32_t b0[4], b1[4];
            int nrow = j * 16 + (lane & 7) + ((lane >> 4) << 3);
            ldmx4(b0[0], b0[1], b0[2], b0[3],
                  kba + (uint32_t)(nrow * PITCH + (lane & 8)) * 2);
            ldmx4(b1[0], b1[1], b1[2], b1[3],
                  kba + (uint32_t)(nrow * PITCH + 16 + (lane & 8)) * 2);

            float c[2][2][4];
            #pragma unroll
            for (int mt = 0; mt < 2; mt++) {
                #pragma unroll
                for (int i = 0; i < 4; i++) { c[mt][0][i] = 0.f; c[mt][1][i] = 0.f; }
                mma16816(c[mt][0], qa[mt][0], &b0[0]);
                mma16816(c[mt][0], qa[mt][1], &b1[0]);
                mma16816(c[mt][1], qa[mt][0], &b0[2]);
                mma16816(c[mt][1], qa[mt][1], &b1[2]);
            }

            // P = 2^score (scores pre-scaled via Q); one MUFU per 2 scores
            uint32_t pa[2][4];
            #pragma unroll
            for (int mt = 0; mt < 2; mt++) {
                pa[mt][0] = exp2h2(c[mt][0][0], c[mt][0][1]);
                pa[mt][1] = exp2h2(c[mt][0][2], c[mt][0][3]);
                pa[mt][2] = exp2h2(c[mt][1][0], c[mt][1][1]);
                pa[mt][3] = exp2h2(c[mt][1][2], c[mt][1][3]);
                mma16816h(Oext[mt], pa[mt], onesh);
            }

            int vrow = j * 16 + (lane & 15);
            uint32_t v0[4], v1[4];
            ldmx4t(v0[0], v0[1], v0[2], v0[3],
                   vba + (uint32_t)(vrow * PITCH + ((lane >> 4) << 3)) * 2);
            ldmx4t(v1[0], v1[1], v1[2], v1[3],
                   vba + (uint32_t)(vrow * PITCH + 16 + ((lane >> 4) << 3)) * 2);

            #pragma unroll
            for (int mt = 0; mt < 2; mt++) {
                mma16816h(O[mt][0], pa[mt], &v0[0]);
                mma16816h(O[mt][1], pa[mt], &v0[2]);
                mma16816h(O[mt][2], pa[mt], &v1[0]);
                mma16816h(O[mt][3], pa[mt], &v1[2]);
            }
        }
        __syncthreads();
    }

    int b = bh >> 3, h = bh & 7;
    float* poz = po + (size_t)z * NTOK * DD;
    float* plz = pl + (size_t)z * NTOK * HH;
    #pragma unroll
    for (int mt = 0; mt < 2; mt++) {
        int r0 = qt * 128 + w * 32 + mt * 16 + (lane >> 2);
        int n  = b * SS + r0;
        size_t base = (size_t)n * DD + h * DHH;
        if ((lane & 3) == 0) {
            plz[(size_t)n * HH + h]       = Oext[mt][0];
            plz[(size_t)(n + 8) * HH + h] = Oext[mt][2];
        }
        #pragma unroll
        for (int nt = 0; nt < 4; nt++) {
            int colo = nt * 8 + 2 * (lane & 3);
            float2 u0; u0.x = O[mt][nt][0]; u0.y = O[mt][nt][1];
            *(float2*)&poz[base + colo] = u0;
            float2 u1; u1.x = O[mt][nt][2]; u1.y = O[mt][nt][3];
            *(float2*)&poz[base + 8 * DD + colo] = u1;
        }
    }
}

// ---------------------------------------------------------------------------
// Launch
// ---------------------------------------------------------------------------
extern "C" void kernel_launch(void* const* d_in, const int* in_sizes, int n_in,
                              void* d_out, int out_size) {
    const float* x      = (const float*)d_in[0];
    const float* ln1_g  = (const float*)d_in[1];
    const float* ln1_b  = (const float*)d_in[2];
    const float* w_qkv  = (const float*)d_in[3];
    const float* b_qkv  = (const float*)d_in[4];
    const float* w_proj = (const float*)d_in[5];
    const float* b_proj = (const float*)d_in[6];
    const float* ln2_g  = (const float*)d_in[7];
    const float* ln2_b  = (const float*)d_in[8];
    const float* w1     = (const float*)d_in[9];
    const float* b1     = (const float*)d_in[10];
    const float* w2     = (const float*)d_in[11];
    const float* b2     = (const float*)d_in[12];
    float* out = (float*)d_out;

    __nv_bfloat16 *yb, *hb, *qb, *kb, *wqkvb, *wprojb, *w1b, *w2b;
    __half *vh;
    float *x1, *po, *pl;
    cudaGetSymbolAddress((void**)&yb,     g_yb);
    cudaGetSymbolAddress((void**)&x1,     g_x1);
    cudaGetSymbolAddress((void**)&hb,     g_hb);
    cudaGetSymbolAddress((void**)&qb,     g_qb);
    cudaGetSymbolAddress((void**)&kb,     g_kb);
    cudaGetSymbolAddress((void**)&vh,     g_vh);
    cudaGetSymbolAddress((void**)&wqkvb,  g_wqkvb);
    cudaGetSymbolAddress((void**)&wprojb, g_wprojb);
    cudaGetSymbolAddress((void**)&w1b,    g_w1b);
    cudaGetSymbolAddress((void**)&w2b,    g_w2b);
    cudaGetSymbolAddress((void**)&po,     g_po);
    cudaGetSymbolAddress((void**)&pl,     g_pl);

    // 0. all weights fp32 -> bf16, one launch
    f2bf_all<<<128, 256>>>(w_qkv, w_proj, w1, w2, wqkvb, wprojb, w1b, w2b);

    // 1. LN1 -> bf16
    ln_kernel<<<NTOK/8, 256>>>(x, ln1_g, ln1_b, yb);
    // 2. QKV GEMM -> Q bf16 (pre-scaled) / K bf16 / V fp16
    gemm_bf<3><<<dim3(768/64, NTOK/128), 256>>>(yb, wqkvb, b_qkv, nullptr, nullptr,
                                                qb, kb, vh, nullptr, 3*DD, DD);
    // 3. split-K attention -> partial O/l (KSPLIT=4)
    attn_mma<<<dim3(BB*HH, SS/128, KSPLIT), 128>>>(qb, kb, vh, po, pl);
    // 4. proj + residual with inline 4-way split-K combine -> x1 fp32
    gemm_bf<4><<<dim3(DD/64, NTOK/128), 256>>>((const __nv_bfloat16*)po, wprojb,
                                               b_proj, x, x1,
                                               nullptr, nullptr, nullptr, pl, DD, DD);
    // 5. LN2 -> bf16
    ln_kernel<<<NTOK/8, 256>>>(x1, ln2_g, ln2_b, yb);
    // 6. FFN1 + silu -> bf16 h
    gemm_bf<2><<<dim3(DFF/64, NTOK/128), 256>>>(yb, w1b, b1, nullptr, nullptr,
                                                hb, nullptr, nullptr, nullptr, DFF, DD);
    // 7. FFN2 + residual -> out fp32
    gemm_bf<1><<<dim3(DD/64, NTOK/128), 256>>>(hb, w2b, b2, x1, out,
                                               nullptr, nullptr, nullptr, nullptr, DD, DFF);
}

// round 15
// speedup vs baseline: 1.0695x; 1.0695x over previous
#include <cuda_runtime.h>
#include <cuda_bf16.h>
#include <cuda_fp16.h>
#include <cstdint>

// Problem constants
#define BB    4
#define SS    2048
#define DD    256
#define HH    8
#define DHH   32
#define DFF   512
#define NTOK  (BB*SS)          // 8192
#define EPS   1e-5f
// softmax scale * log2(e), folded into Q at QKV epilogue
#define ATT_SC2 0.25503540f
#define KSPLIT 2
#define KSEG   (SS/KSPLIT)     // 1024

// smem row pitch in halves (80B): conflict-free + 16B-aligned rows for ldmatrix
#define PITCH 40

// ---------------------------------------------------------------------------
// Scratch (device globals; no allocations allowed)
// ---------------------------------------------------------------------------
__device__ __nv_bfloat16 g_yb [NTOK * DD];        // LN output (bf16)
__device__ float         g_x1 [NTOK * DD];        // residual after attention
__device__ __nv_bfloat16 g_hb [NTOK * DFF];       // FFN hidden (bf16)
__device__ __nv_bfloat16 g_qb[BB*HH * SS * DHH];  // Q bf16 (pre-scaled) [bh][s][32]
__device__ __nv_bfloat16 g_kb[BB*HH * SS * DHH];  // K bf16
__device__ __half        g_vh[BB*HH * SS * DHH];  // V fp16
__device__ __nv_bfloat16 g_wqkvb[3*DD * DD];      // bf16 weights
__device__ __nv_bfloat16 g_wprojb[DD * DD];
__device__ __nv_bfloat16 g_w1b[DFF * DD];
__device__ __nv_bfloat16 g_w2b[DD * DFF];
__device__ float g_po[KSPLIT * NTOK * DD];        // split-K partial O (fp32)
__device__ float g_pl[KSPLIT * NTOK * HH];        // split-K partial l

__device__ __forceinline__ uint32_t packbf(float lo, float hi) {
    __nv_bfloat162 t = __floats2bfloat162_rn(lo, hi);
    return *reinterpret_cast<uint32_t*>(&t);
}
// pack 2 fp32 exponent args -> f16x2, then 2^x on both halves (1 MUFU op)
__device__ __forceinline__ uint32_t exp2h2(float lo, float hi) {
    uint32_t d;
    asm("cvt.rn.f16x2.f32 %0, %1, %2;" : "=r"(d) : "f"(hi), "f"(lo));
    asm("ex2.approx.f16x2 %0, %0;" : "+r"(d));
    return d;
}
__device__ __forceinline__ void cpa16(uint32_t dst, const void* src) {
    asm volatile("cp.async.cg.shared.global [%0], [%1], 16;" :: "r"(dst), "l"(src));
}

__device__ __forceinline__ float warp_sum(float v) {
    #pragma unroll
    for (int o = 16; o > 0; o >>= 1) v += __shfl_xor_sync(0xffffffffu, v, o);
    return v;
}

// ---------------------------------------------------------------------------
// Fused: weight fp32->bf16 conversion (blocks 0..127) + LayerNorm1 (rest).
// Both sides use 256 threads.
// ---------------------------------------------------------------------------
__global__ __launch_bounds__(256) void f2bf_ln(
        const float* __restrict__ s0, const float* __restrict__ s1,
        const float* __restrict__ s2, const float* __restrict__ s3,
        __nv_bfloat16* __restrict__ d0, __nv_bfloat16* __restrict__ d1,
        __nv_bfloat16* __restrict__ d2, __nv_bfloat16* __restrict__ d3,
        const float* __restrict__ x, const float* __restrict__ g,
        const float* __restrict__ b, __nv_bfloat16* __restrict__ y) {
    if (blockIdx.x < 128) {
        int i = blockIdx.x * 256 + threadIdx.x;     // 0..32767
        int idx = i * 16;
        const float* src; __nv_bfloat16* dst; int off;
        if (idx < 196608)      { src = s0; dst = d0; off = idx; }
        else if (idx < 262144) { src = s1; dst = d1; off = idx - 196608; }
        else if (idx < 393216) { src = s2; dst = d2; off = idx - 262144; }
        else                   { src = s3; dst = d3; off = idx - 393216; }
        float4 v0 = *(const float4*)(src + off);
        float4 v1 = *(const float4*)(src + off + 4);
        float4 v2 = *(const float4*)(src + off + 8);
        float4 v3 = *(const float4*)(src + off + 12);
        uint4 o0, o1;
        o0.x = packbf(v0.x, v0.y); o0.y = packbf(v0.z, v0.w);
        o0.z = packbf(v1.x, v1.y); o0.w = packbf(v1.z, v1.w);
        o1.x = packbf(v2.x, v2.y); o1.y = packbf(v2.z, v2.w);
        o1.z = packbf(v3.x, v3.y); o1.w = packbf(v3.z, v3.w);
        *(uint4*)(dst + off)     = o0;
        *(uint4*)(dst + off + 8) = o1;
        return;
    }
    // LN part
    int row  = (blockIdx.x - 128) * 8 + (threadIdx.x >> 5);
    int lane = threadIdx.x & 31;
    const float* xr = x + (size_t)row * DD + lane * 8;

    float4 v0 = *(const float4*)(xr);
    float4 v1 = *(const float4*)(xr + 4);
    float d[8] = {v0.x, v0.y, v0.z, v0.w, v1.x, v1.y, v1.z, v1.w};

    float s = d[0]+d[1]+d[2]+d[3]+d[4]+d[5]+d[6]+d[7];
    float mean = warp_sum(s) * (1.0f / DD);

    float ss = 0.f;
    #pragma unroll
    for (int j = 0; j < 8; j++) { d[j] -= mean; ss += d[j] * d[j]; }
    float var = warp_sum(ss) * (1.0f / DD);
    float r = rsqrtf(var + EPS);

    float4 g0 = *(const float4*)(g + lane * 8);
    float4 g1 = *(const float4*)(g + lane * 8 + 4);
    float4 b0 = *(const float4*)(b + lane * 8);
    float4 b1 = *(const float4*)(b + lane * 8 + 4);
    float gg[8] = {g0.x, g0.y, g0.z, g0.w, g1.x, g1.y, g1.z, g1.w};
    float bb2[8] = {b0.x, b0.y, b0.z, b0.w, b1.x, b1.y, b1.z, b1.w};

    float o[8];
    #pragma unroll
    for (int j = 0; j < 8; j++) o[j] = d[j] * r * gg[j] + bb2[j];

    uint4 pk;
    pk.x = packbf(o[0], o[1]);
    pk.y = packbf(o[2], o[3]);
    pk.z = packbf(o[4], o[5]);
    pk.w = packbf(o[6], o[7]);
    *(uint4*)&y[(size_t)row * DD + lane * 8] = pk;
}

// ---------------------------------------------------------------------------
// LayerNorm -> bf16: one WARP per row (8 rows per 256-thread block)
// ---------------------------------------------------------------------------
__global__ __launch_bounds__(256) void ln_kernel(const float* __restrict__ x,
                                                 const float* __restrict__ g,
                                                 const float* __restrict__ b,
                                                 __nv_bfloat16* __restrict__ y) {
    int row  = blockIdx.x * 8 + (threadIdx.x >> 5);
    int lane = threadIdx.x & 31;
    const float* xr = x + (size_t)row * DD + lane * 8;

    float4 v0 = *(const float4*)(xr);
    float4 v1 = *(const float4*)(xr + 4);
    float d[8] = {v0.x, v0.y, v0.z, v0.w, v1.x, v1.y, v1.z, v1.w};

    float s = d[0]+d[1]+d[2]+d[3]+d[4]+d[5]+d[6]+d[7];
    float mean = warp_sum(s) * (1.0f / DD);

    float ss = 0.f;
    #pragma unroll
    for (int j = 0; j < 8; j++) { d[j] -= mean; ss += d[j] * d[j]; }
    float var = warp_sum(ss) * (1.0f / DD);
    float r = rsqrtf(var + EPS);

    float4 g0 = *(const float4*)(g + lane * 8);
    float4 g1 = *(const float4*)(g + lane * 8 + 4);
    float4 b0 = *(const float4*)(b + lane * 8);
    float4 b1 = *(const float4*)(b + lane * 8 + 4);
    float gg[8] = {g0.x, g0.y, g0.z, g0.w, g1.x, g1.y, g1.z, g1.w};
    float bb2[8] = {b0.x, b0.y, b0.z, b0.w, b1.x, b1.y, b1.z, b1.w};

    float o[8];
    #pragma unroll
    for (int j = 0; j < 8; j++) o[j] = d[j] * r * gg[j] + bb2[j];

    uint4 pk;
    pk.x = packbf(o[0], o[1]);
    pk.y = packbf(o[2], o[3]);
    pk.z = packbf(o[4], o[5]);
    pk.w = packbf(o[6], o[7]);
    *(uint4*)&y[(size_t)row * DD + lane * 8] = pk;
}

// ---------------------------------------------------------------------------
// mma helpers
// ---------------------------------------------------------------------------
__device__ __forceinline__ void ldmx4(uint32_t& r0, uint32_t& r1,
                                      uint32_t& r2, uint32_t& r3, uint32_t a) {
    asm volatile("ldmatrix.sync.aligned.m8n8.x4.shared.b16 {%0,%1,%2,%3}, [%4];\n"
                 : "=r"(r0), "=r"(r1), "=r"(r2), "=r"(r3) : "r"(a));
}
__device__ __forceinline__ void ldmx4t(uint32_t& r0, uint32_t& r1,
                                       uint32_t& r2, uint32_t& r3, uint32_t a) {
    asm volatile("ldmatrix.sync.aligned.m8n8.x4.trans.shared.b16 {%0,%1,%2,%3}, [%4];\n"
                 : "=r"(r0), "=r"(r1), "=r"(r2), "=r"(r3) : "r"(a));
}
__device__ __forceinline__ void mma16816(float* c, const uint32_t* a, const uint32_t* b) {
    asm volatile("mma.sync.aligned.m16n8k16.row.col.f32.bf16.bf16.f32 "
                 "{%0,%1,%2,%3}, {%4,%5,%6,%7}, {%8,%9}, {%0,%1,%2,%3};\n"
                 : "+f"(c[0]), "+f"(c[1]), "+f"(c[2]), "+f"(c[3])
                 : "r"(a[0]), "r"(a[1]), "r"(a[2]), "r"(a[3]),
                   "r"(b[0]), "r"(b[1]));
}
__device__ __forceinline__ void mma16816h(float* c, const uint32_t* a, const uint32_t* b) {
    asm volatile("mma.sync.aligned.m16n8k16.row.col.f32.f16.f16.f32 "
                 "{%0,%1,%2,%3}, {%4,%5,%6,%7}, {%8,%9}, {%0,%1,%2,%3};\n"
                 : "+f"(c[0]), "+f"(c[1]), "+f"(c[2]), "+f"(c[3])
                 : "r"(a[0]), "r"(a[1]), "r"(a[2]), "r"(a[3]),
                   "r"(b[0]), "r"(b[1]));
}

// ---------------------------------------------------------------------------
// bf16 tensor-core NT GEMM (R11 shape): 128x64 tile, BK=32, 256 threads,
// 2-stage cp.async pipeline. Warp tile 32x32.
// MODE 1: fp32 out + residual
// MODE 2: silu -> bf16 out
// MODE 3: qkv scatter (Q bf16 pre-scaled by ATT_SC2, K bf16, V fp16)
// MODE 4: like 1, but A = split-K partial O (2 x fp32) combined inline w/ pl
// ---------------------------------------------------------------------------
template<int MODE>
__global__ __launch_bounds__(256) void gemm_bf(
        const __nv_bfloat16* __restrict__ A,
        const __nv_bfloat16* __restrict__ W,
        const float* __restrict__ bias,
        const float* __restrict__ res,
        float* __restrict__ C,
        __nv_bfloat16* __restrict__ Ob,
        __nv_bfloat16* __restrict__ Kb,
        __half* __restrict__ Vh,
        const float* __restrict__ pl,
        int M, int K) {
    __shared__ __nv_bfloat16 As[2][128 * PITCH];
    __shared__ __nv_bfloat16 Bs[2][64 * PITCH];

    int t = threadIdx.x, w = t >> 5, lane = t & 31;
    int wm = w >> 1;
    int wn = w & 1;
    int row0 = blockIdx.y * 128;
    int col0 = blockIdx.x * 64;

    uint32_t ab_[2] = { (uint32_t)__cvta_generic_to_shared(As[0]),
                        (uint32_t)__cvta_generic_to_shared(As[1]) };
    uint32_t bb_[2] = { (uint32_t)__cvta_generic_to_shared(Bs[0]),
                        (uint32_t)__cvta_generic_to_shared(Bs[1]) };

    // cp.async indices: A 2 per thread, B 1 per thread
    int ar = t >> 1, ac = (t & 1) * 2;
    int br = t >> 2, bc = t & 3;
    uint32_t soA0 = (uint32_t)(ar * PITCH + ac * 8) * 2;
    uint32_t soA1 = (uint32_t)(ar * PITCH + (ac + 1) * 8) * 2;
    uint32_t soB  = (uint32_t)(br * PITCH + bc * 8) * 2;
    const __nv_bfloat16* asrc = A + (size_t)(row0 + ar) * K;
    const __nv_bfloat16* bsrc = W + (size_t)(col0 + br) * K;

    // MODE 4: inline split-K combine loader state (2 threads per row)
    int ar4 = t >> 1, ac4 = (t & 1) * 16;
    int n4  = row0 + ar4;
    const float* po0 = reinterpret_cast<const float*>(A) + (size_t)n4 * DD;
    const float* po1 = po0 + (size_t)NTOK * DD;
    float4 ra[4], rb[4];
    float pl0 = 0.f, pl1 = 0.f;

    float c[2][4][4];
    #pragma unroll
    for (int i = 0; i < 2; i++)
        #pragma unroll
        for (int j = 0; j < 4; j++)
            #pragma unroll
            for (int k = 0; k < 4; k++) c[i][j][k] = 0.f;

    // prologue
    cpa16(bb_[0] + soB, bsrc + bc * 8);
    if (MODE != 4) {
        cpa16(ab_[0] + soA0, asrc + ac * 8);
        cpa16(ab_[0] + soA1, asrc + (ac + 1) * 8);
    }
    asm volatile("cp.async.commit_group;");

    if (MODE == 4) {
        const float* s0 = po0 + ac4;
        const float* s1 = po1 + ac4;
        #pragma unroll
        for (int i = 0; i < 4; i++) {
            ra[i] = *(const float4*)(s0 + i * 4);
            rb[i] = *(const float4*)(s1 + i * 4);
        }
        pl0 = pl[(size_t)n4 * HH + 0];
        pl1 = pl[(size_t)NTOK * HH + (size_t)n4 * HH + 0];
        float inv = 1.0f / (pl0 + pl1);
        uint4 o0, o1;
        o0.x = packbf((ra[0].x+rb[0].x)*inv, (ra[0].y+rb[0].y)*inv);
        o0.y = packbf((ra[0].z+rb[0].z)*inv, (ra[0].w+rb[0].w)*inv);
        o0.z = packbf((ra[1].x+rb[1].x)*inv, (ra[1].y+rb[1].y)*inv);
        o0.w = packbf((ra[1].z+rb[1].z)*inv, (ra[1].w+rb[1].w)*inv);
        o1.x = packbf((ra[2].x+rb[2].x)*inv, (ra[2].y+rb[2].y)*inv);
        o1.y = packbf((ra[2].z+rb[2].z)*inv, (ra[2].w+rb[2].w)*inv);
        o1.z = packbf((ra[3].x+rb[3].x)*inv, (ra[3].y+rb[3].y)*inv);
        o1.w = packbf((ra[3].z+rb[3].z)*inv, (ra[3].w+rb[3].w)*inv);
        *(uint4*)&As[0][ar4 * PITCH + ac4]     = o0;
        *(uint4*)&As[0][ar4 * PITCH + ac4 + 8] = o1;
    }

    int NK = K >> 5;
    for (int it = 0; it < NK; it++) {
        int cur = it & 1;
        int nb = cur ^ 1;
        if (it + 1 < NK) {
            int k0 = (it + 1) * 32;
            cpa16(bb_[nb] + soB, bsrc + k0 + bc * 8);
            if (MODE != 4) {
                cpa16(ab_[nb] + soA0, asrc + k0 + ac * 8);
                cpa16(ab_[nb] + soA1, asrc + k0 + (ac + 1) * 8);
            }
            asm volatile("cp.async.commit_group;");
            asm volatile("cp.async.wait_group 1;");
        } else {
            asm volatile("cp.async.wait_group 0;");
        }
        __syncthreads();

        // MODE 4: issue next A-tile partial loads (overlap with mma below)
        if (MODE == 4 && it + 1 < NK) {
            const float* s0 = po0 + (it + 1) * 32 + ac4;
            const float* s1 = po1 + (it + 1) * 32 + ac4;
            #pragma unroll
            for (int i = 0; i < 4; i++) {
                ra[i] = *(const float4*)(s0 + i * 4);
                rb[i] = *(const float4*)(s1 + i * 4);
            }
            pl0 = pl[(size_t)n4 * HH + (it + 1)];
            pl1 = pl[(size_t)NTOK * HH + (size_t)n4 * HH + (it + 1)];
        }

        uint32_t abase = ab_[cur], bbase = bb_[cur];
        uint32_t bf[2][2][4];
        #pragma unroll
        for (int nt = 0; nt < 2; nt++) {
            int nrow = wn * 32 + nt * 16 + (lane & 7) + ((lane >> 4) << 3);
            #pragma unroll
            for (int ks = 0; ks < 2; ks++) {
                uint32_t ad = bbase + (uint32_t)(nrow * PITCH + ks * 16 + (lane & 8)) * 2;
                ldmx4(bf[nt][ks][0], bf[nt][ks][1], bf[nt][ks][2], bf[nt][ks][3], ad);
            }
        }
        #pragma unroll
        for (int mt = 0; mt < 2; mt++) {
            int arow = wm * 32 + mt * 16 + (lane & 15);
            #pragma unroll
            for (int ks = 0; ks < 2; ks++) {
                uint32_t af[4];
                uint32_t ad = abase + (uint32_t)(arow * PITCH + ks * 16 + ((lane >> 4) << 3)) * 2;
                ldmx4(af[0], af[1], af[2], af[3], ad);
                #pragma unroll
                for (int nt = 0; nt < 2; nt++) {
                    mma16816(c[mt][2 * nt],     af, &bf[nt][ks][0]);
                    mma16816(c[mt][2 * nt + 1], af, &bf[nt][ks][2]);
                }
            }
        }

        // MODE 4: combine + store next A tile into the other buffer
        if (MODE == 4 && it + 1 < NK) {
            float inv = 1.0f / (pl0 + pl1);
            uint4 o0, o1;
            o0.x = packbf((ra[0].x+rb[0].x)*inv, (ra[0].y+rb[0].y)*inv);
            o0.y = packbf((ra[0].z+rb[0].z)*inv, (ra[0].w+rb[0].w)*inv);
            o0.z = packbf((ra[1].x+rb[1].x)*inv, (ra[1].y+rb[1].y)*inv);
            o0.w = packbf((ra[1].z+rb[1].z)*inv, (ra[1].w+rb[1].w)*inv);
            o1.x = packbf((ra[2].x+rb[2].x)*inv, (ra[2].y+rb[2].y)*inv);
            o1.y = packbf((ra[2].z+rb[2].z)*inv, (ra[2].w+rb[2].w)*inv);
            o1.z = packbf((ra[3].x+rb[3].x)*inv, (ra[3].y+rb[3].y)*inv);
            o1.w = packbf((ra[3].z+rb[3].z)*inv, (ra[3].w+rb[3].w)*inv);
            *(uint4*)&As[nb][ar4 * PITCH + ac4]     = o0;
            *(uint4*)&As[nb][ar4 * PITCH + ac4 + 8] = o1;
        }
        __syncthreads();
    }

    #pragma unroll
    for (int mt = 0; mt < 2; mt++) {
        #pragma unroll
        for (int half = 0; half < 2; half++) {
            int row = row0 + wm * 32 + mt * 16 + (lane >> 2) + half * 8;
            #pragma unroll
            for (int n8 = 0; n8 < 4; n8++) {
                int col = col0 + wn * 32 + n8 * 8 + 2 * (lane & 3);
                float v0 = c[mt][n8][2 * half]     + bias[col];
                float v1 = c[mt][n8][2 * half + 1] + bias[col + 1];
                if (MODE == 1 || MODE == 4) {
                    const float2 r2 = *(const float2*)&res[(size_t)row * M + col];
                    float2 o; o.x = v0 + r2.x; o.y = v1 + r2.y;
                    *(float2*)&C[(size_t)row * M + col] = o;
                } else if (MODE == 2) {
                    v0 = v0 * (1.0f / (1.0f + __expf(-v0)));
                    v1 = v1 * (1.0f / (1.0f + __expf(-v1)));
                    *(__nv_bfloat162*)&Ob[(size_t)row * M + col] =
                        __floats2bfloat162_rn(v0, v1);
                } else {
                    int seg = col >> 8, rem = col & 255;
                    int h = rem >> 5, d = rem & 31;
                    int b = row >> 11, s = row & 2047;
                    size_t di = ((size_t)(b * HH + h) * SS + s) * DHH + d;
                    if (seg == 0) {
                        *(__nv_bfloat162*)&Ob[di] =
                            __floats2bfloat162_rn(v0 * ATT_SC2, v1 * ATT_SC2);
                    } else if (seg == 1) {
                        *(__nv_bfloat162*)&Kb[di] = __floats2bfloat162_rn(v0, v1);
                    } else {
                        *(__half2*)&Vh[di] = __floats2half2_rn(v0, v1);
                    }
                }
            }
        }
    }
}

// ---------------------------------------------------------------------------
// Split-K tensor-core flash attention.
// S-mma: bf16 (Q pre-scaled). P = ex2.f16x2 of scores. PV-mma: fp16.
// grid (BH=32, S/128=16, KSPLIT=2), block 128 (4 warps; warp owns 32 q rows).
// K/V tiles: 3-stage cp.async ring, ONE __syncthreads per iteration.
// Writes UNNORMALIZED partial O (fp32) and partial l.
// ---------------------------------------------------------------------------
__global__ __launch_bounds__(128) void attn_mma(const __nv_bfloat16* __restrict__ Qb,
                                                const __nv_bfloat16* __restrict__ Kb,
                                                const __half* __restrict__ Vh,
                                                float* __restrict__ po,
                                                float* __restrict__ pl) {
    __shared__ __nv_bfloat16 Qs[128 * PITCH];
    __shared__ __nv_bfloat16 Ks[3][64 * PITCH];
    __shared__ __half        Vs[3][64 * PITCH];

    int bh = blockIdx.x;
    int qt = blockIdx.y;
    int z  = blockIdx.z;
    int t = threadIdx.x, w = t >> 5, lane = t & 31;

    const __nv_bfloat16* qsrc = Qb + ((size_t)bh * SS + qt * 128) * DHH;
    const __nv_bfloat16* ksrc = Kb + ((size_t)bh * SS + z * KSEG) * DHH;
    const __half*        vsrc = Vh + ((size_t)bh * SS + z * KSEG) * DHH;

    uint32_t qbase = (uint32_t)__cvta_generic_to_shared(Qs);
    uint32_t kb_[3] = { (uint32_t)__cvta_generic_to_shared(Ks[0]),
                        (uint32_t)__cvta_generic_to_shared(Ks[1]),
                        (uint32_t)__cvta_generic_to_shared(Ks[2]) };
    uint32_t vb_[3] = { (uint32_t)__cvta_generic_to_shared(Vs[0]),
                        (uint32_t)__cvta_generic_to_shared(Vs[1]),
                        (uint32_t)__cvta_generic_to_shared(Vs[2]) };

    #pragma unroll
    for (int i = t; i < 512; i += 128) {
        int r = i >> 2, s = i & 3;
        *(uint4*)&Qs[r * PITCH + s * 8] = *(const uint4*)&qsrc[r * 32 + s * 8];
    }

    int lr = t >> 2, ls = t & 3;
    uint32_t so0 = (uint32_t)(lr * PITCH + ls * 8) * 2;
    uint32_t so1 = (uint32_t)((lr + 32) * PITCH + ls * 8) * 2;

    // prologue: stage 0 and stage 1 (two commit groups)
    cpa16(kb_[0] + so0, &ksrc[lr * 32 + ls * 8]);
    cpa16(kb_[0] + so1, &ksrc[(lr + 32) * 32 + ls * 8]);
    cpa16(vb_[0] + so0, &vsrc[lr * 32 + ls * 8]);
    cpa16(vb_[0] + so1, &vsrc[(lr + 32) * 32 + ls * 8]);
    asm volatile("cp.async.commit_group;");
    cpa16(kb_[1] + so0, &ksrc[(64 + lr) * 32 + ls * 8]);
    cpa16(kb_[1] + so1, &ksrc[(64 + lr + 32) * 32 + ls * 8]);
    cpa16(vb_[1] + so0, &vsrc[(64 + lr) * 32 + ls * 8]);
    cpa16(vb_[1] + so1, &vsrc[(64 + lr + 32) * 32 + ls * 8]);
    asm volatile("cp.async.commit_group;");

    __syncthreads();   // Q ready

    uint32_t qa[2][2][4];
    #pragma unroll
    for (int mt = 0; mt < 2; mt++) {
        int row = w * 32 + mt * 16 + (lane & 15);
        #pragma unroll
        for (int ks = 0; ks < 2; ks++) {
            uint32_t a = qbase + (uint32_t)(row * PITCH + ks * 16 + ((lane >> 4) << 3)) * 2;
            ldmx4(qa[mt][ks][0], qa[mt][ks][1], qa[mt][ks][2], qa[mt][ks][3], a);
        }
    }

    float O[2][4][4];
    #pragma unroll
    for (int mt = 0; mt < 2; mt++)
        #pragma unroll
        for (int i = 0; i < 4; i++)
            #pragma unroll
            for (int j = 0; j < 4; j++) O[mt][i][j] = 0.f;
    float Oext[2][4] = {{0.f,0.f,0.f,0.f},{0.f,0.f,0.f,0.f}};
    const uint32_t onesh[2] = {0x3C003C00u, 0x3C003C00u};   // f16 1.0 x2

    const int NIT = KSEG / 64;   // 16
    for (int it = 0; it < NIT; it++) {
        // make stage it ready (leave at most the next stage's group outstanding)
        if (it + 1 < NIT) {
            asm volatile("cp.async.wait_group 1;");
        } else {
            asm volatile("cp.async.wait_group 0;");
        }
        __syncthreads();   // single barrier: data visible + prior stage readers done

        // prefetch stage it+2 into ring slot (it+2)%3 (last read at iter it-1)
        if (it + 2 < NIT) {
            int st = (it + 2) % 3;
            int koff = (it + 2) * 64;
            cpa16(kb_[st] + so0, &ksrc[(koff + lr) * 32 + ls * 8]);
            cpa16(kb_[st] + so1, &ksrc[(koff + lr + 32) * 32 + ls * 8]);
            cpa16(vb_[st] + so0, &vsrc[(koff + lr) * 32 + ls * 8]);
            cpa16(vb_[st] + so1, &vsrc[(koff + lr + 32) * 32 + ls * 8]);
            asm volatile("cp.async.commit_group;");
        }

        int cur = it % 3;
        uint32_t kba = kb_[cur], vba = vb_[cur];
        #pragma unroll
        for (int j = 0; j < 4; j++) {            // 16-key slabs
            uint32_t b0[4], b1[4];
            int nrow = j * 16 + (lane & 7) + ((lane >> 4) << 3);
            ldmx4(b0[0], b0[1], b0[2], b0[3],
                  kba + (uint32_t)(nrow * PITCH + (lane & 8)) * 2);
            ldmx4(b1[0], b1[1], b1[2], b1[3],
                  kba + (uint32_t)(nrow * PITCH + 16 + (lane & 8)) * 2);

            float c[2][2][4];
            #pragma unroll
            for (int mt = 0; mt < 2; mt++) {
                #pragma unroll
                for (int i = 0; i < 4; i++) { c[mt][0][i] = 0.f; c[mt][1][i] = 0.f; }
                mma16816(c[mt][0], qa[mt][0], &b0[0]);
                mma16816(c[mt][0], qa[mt][1], &b1[0]);
                mma16816(c[mt][1], qa[mt][0], &b0[2]);
                mma16816(c[mt][1], qa[mt][1], &b1[2]);
            }

            // P = 2^score (scores pre-scaled via Q); one MUFU per 2 scores
            uint32_t pa[2][4];
            #pragma unroll
            for (int mt = 0; mt < 2; mt++) {
                pa[mt][0] = exp2h2(c[mt][0][0], c[mt][0][1]);
                pa[mt][1] = exp2h2(c[mt][0][2], c[mt][0][3]);
                pa[mt][2] = exp2h2(c[mt][1][0], c[mt][1][1]);
                pa[mt][3] = exp2h2(c[mt][1][2], c[mt][1][3]);
                mma16816h(Oext[mt], pa[mt], onesh);
            }

            int vrow = j * 16 + (lane & 15);
            uint32_t v0[4], v1[4];
            ldmx4t(v0[0], v0[1], v0[2], v0[3],
                   vba + (uint32_t)(vrow * PITCH + ((lane >> 4) << 3)) * 2);
            ldmx4t(v1[0], v1[1], v1[2], v1[3],
                   vba + (uint32_t)(vrow * PITCH + 16 + ((lane >> 4) << 3)) * 2);

            #pragma unroll
            for (int mt = 0; mt < 2; mt++) {
                mma16816h(O[mt][0], pa[mt], &v0[0]);
                mma16816h(O[mt][1], pa[mt], &v0[2]);
                mma16816h(O[mt][2], pa[mt], &v1[0]);
                mma16816h(O[mt][3], pa[mt], &v1[2]);
            }
        }
    }

    int b = bh >> 3, h = bh & 7;
    float* poz = po + (size_t)z * NTOK * DD;
    float* plz = pl + (size_t)z * NTOK * HH;
    #pragma unroll
    for (int mt = 0; mt < 2; mt++) {
        int r0 = qt * 128 + w * 32 + mt * 16 + (lane >> 2);
        int n  = b * SS + r0;
        size_t base = (size_t)n * DD + h * DHH;
        if ((lane & 3) == 0) {
            plz[(size_t)n * HH + h]       = Oext[mt][0];
            plz[(size_t)(n + 8) * HH + h] = Oext[mt][2];
        }
        #pragma unroll
        for (int nt = 0; nt < 4; nt++) {
            int colo = nt * 8 + 2 * (lane & 3);
            float2 u0; u0.x = O[mt][nt][0]; u0.y = O[mt][nt][1];
            *(float2*)&poz[base + colo] = u0;
            float2 u1; u1.x = O[mt][nt][2]; u1.y = O[mt][nt][3];
            *(float2*)&poz[base + 8 * DD + colo] = u1;
        }
    }
}

// ---------------------------------------------------------------------------
// Launch
// ---------------------------------------------------------------------------
extern "C" void kernel_launch(void* const* d_in, const int* in_sizes, int n_in,
                              void* d_out, int out_size) {
    const float* x      = (const float*)d_in[0];
    const float* ln1_g  = (const float*)d_in[1];
    const float* ln1_b  = (const float*)d_in[2];
    const float* w_qkv  = (const float*)d_in[3];
    const float* b_qkv  = (const float*)d_in[4];
    const float* w_proj = (const float*)d_in[5];
    const float* b_proj = (const float*)d_in[6];
    const float* ln2_g  = (const float*)d_in[7];
    const float* ln2_b  = (const float*)d_in[8];
    const float* w1     = (const float*)d_in[9];
    const float* b1     = (const float*)d_in[10];
    const float* w2     = (const float*)d_in[11];
    const float* b2     = (const float*)d_in[12];
    float* out = (float*)d_out;

    __nv_bfloat16 *yb, *hb, *qb, *kb, *wqkvb, *wprojb, *w1b, *w2b;
    __half *vh;
    float *x1, *po, *pl;
    cudaGetSymbolAddress((void**)&yb,     g_yb);
    cudaGetSymbolAddress((void**)&x1,     g_x1);
    cudaGetSymbolAddress((void**)&hb,     g_hb);
    cudaGetSymbolAddress((void**)&qb,     g_qb);
    cudaGetSymbolAddress((void**)&kb,     g_kb);
    cudaGetSymbolAddress((void**)&vh,     g_vh);
    cudaGetSymbolAddress((void**)&wqkvb,  g_wqkvb);
    cudaGetSymbolAddress((void**)&wprojb, g_wprojb);
    cudaGetSymbolAddress((void**)&w1b,    g_w1b);
    cudaGetSymbolAddress((void**)&w2b,    g_w2b);
    cudaGetSymbolAddress((void**)&po,     g_po);
    cudaGetSymbolAddress((void**)&pl,     g_pl);

    // 0+1. fused weight conversion + LN1 (one launch)
    f2bf_ln<<<128 + NTOK/8, 256>>>(w_qkv, w_proj, w1, w2,
                                   wqkvb, wprojb, w1b, w2b,
                                   x, ln1_g, ln1_b, yb);
    // 2. QKV GEMM -> Q bf16 (pre-scaled) / K bf16 / V fp16
    gemm_bf<3><<<dim3(768/64, NTOK/128), 256>>>(yb, wqkvb, b_qkv, nullptr, nullptr,
                                                qb, kb, vh, nullptr, 3*DD, DD);
    // 3. split-K attention -> partial O/l (KSPLIT=2)
    attn_mma<<<dim3(BB*HH, SS/128, KSPLIT), 128>>>(qb, kb, vh, po, pl);
    // 4. proj + residual with inline 2-way split-K combine -> x1 fp32
    gemm_bf<4><<<dim3(DD/64, NTOK/128), 256>>>((const __nv_bfloat16*)po, wprojb,
                                               b_proj, x, x1,
                                               nullptr, nullptr, nullptr, pl, DD, DD);
    // 5. LN2 -> bf16
    ln_kernel<<<NTOK/8, 256>>>(x1, ln2_g, ln2_b, yb);
    // 6. FFN1 + silu -> bf16 h
    gemm_bf<2><<<dim3(DFF/64, NTOK/128), 256>>>(yb, w1b, b1, nullptr, nullptr,
                                                hb, nullptr, nullptr, nullptr, DFF, DD);
    // 7. FFN2 + residual -> out fp32
    gemm_bf<1><<<dim3(DD/64, NTOK/128), 256>>>(hb, w2b, b2, x1, out,
                                               nullptr, nullptr, nullptr, nullptr, DD, DFF);
}

// round 16
// speedup vs baseline: 1.1277x; 1.0544x over previous
#include <cuda_runtime.h>
#include <cuda_bf16.h>
#include <cuda_fp16.h>
#include <cstdint>

// Problem constants
#define BB    4
#define SS    2048
#define DD    256
#define HH    8
#define DHH   32
#define DFF   512
#define NTOK  (BB*SS)          // 8192
#define EPS   1e-5f
// softmax scale * log2(e), folded into Q at QKV epilogue
#define ATT_SC2 0.25503540f
#define KSPLIT 2
#define KSEG   (SS/KSPLIT)     // 1024

// smem row pitch in halves (80B): conflict-free + 16B-aligned rows for ldmatrix
#define PITCH 40

// ---------------------------------------------------------------------------
// Scratch (device globals; no allocations allowed)
// ---------------------------------------------------------------------------
__device__ __nv_bfloat16 g_yb [NTOK * DD];        // LN output (bf16)
__device__ __nv_bfloat16 g_ctxb[NTOK * DD];       // combined attention ctx (bf16)
__device__ float         g_x1 [NTOK * DD];        // residual after attention
__device__ __nv_bfloat16 g_hb [NTOK * DFF];       // FFN hidden (bf16)
__device__ __nv_bfloat16 g_qb[BB*HH * SS * DHH];  // Q bf16 (pre-scaled) [bh][s][32]
__device__ __nv_bfloat16 g_kb[BB*HH * SS * DHH];  // K bf16
__device__ __half        g_vh[BB*HH * SS * DHH];  // V fp16
__device__ __nv_bfloat16 g_wqkvb[3*DD * DD];      // bf16 weights
__device__ __nv_bfloat16 g_wprojb[DD * DD];
__device__ __nv_bfloat16 g_w1b[DFF * DD];
__device__ __nv_bfloat16 g_w2b[DD * DFF];
__device__ float g_po[KSPLIT * NTOK * DD];        // split-K partial O (fp32)
__device__ float g_pl[KSPLIT * NTOK * HH];        // split-K partial l

__device__ __forceinline__ uint32_t packbf(float lo, float hi) {
    __nv_bfloat162 t = __floats2bfloat162_rn(lo, hi);
    return *reinterpret_cast<uint32_t*>(&t);
}
// pack 2 fp32 exponent args -> f16x2, then 2^x on both halves (1 MUFU op)
__device__ __forceinline__ uint32_t exp2h2(float lo, float hi) {
    uint32_t d;
    asm("cvt.rn.f16x2.f32 %0, %1, %2;" : "=r"(d) : "f"(hi), "f"(lo));
    asm("ex2.approx.f16x2 %0, %0;" : "+r"(d));
    return d;
}
__device__ __forceinline__ void cpa16(uint32_t dst, const void* src) {
    asm volatile("cp.async.cg.shared.global [%0], [%1], 16;" :: "r"(dst), "l"(src));
}

__device__ __forceinline__ float warp_sum(float v) {
    #pragma unroll
    for (int o = 16; o > 0; o >>= 1) v += __shfl_xor_sync(0xffffffffu, v, o);
    return v;
}

// ---------------------------------------------------------------------------
// Fused: weight fp32->bf16 conversion (blocks 0..127) + LayerNorm1 (rest).
// ---------------------------------------------------------------------------
__global__ __launch_bounds__(256) void f2bf_ln(
        const float* __restrict__ s0, const float* __restrict__ s1,
        const float* __restrict__ s2, const float* __restrict__ s3,
        __nv_bfloat16* __restrict__ d0, __nv_bfloat16* __restrict__ d1,
        __nv_bfloat16* __restrict__ d2, __nv_bfloat16* __restrict__ d3,
        const float* __restrict__ x, const float* __restrict__ g,
        const float* __restrict__ b, __nv_bfloat16* __restrict__ y) {
    if (blockIdx.x < 128) {
        int i = blockIdx.x * 256 + threadIdx.x;     // 0..32767
        int idx = i * 16;
        const float* src; __nv_bfloat16* dst; int off;
        if (idx < 196608)      { src = s0; dst = d0; off = idx; }
        else if (idx < 262144) { src = s1; dst = d1; off = idx - 196608; }
        else if (idx < 393216) { src = s2; dst = d2; off = idx - 262144; }
        else                   { src = s3; dst = d3; off = idx - 393216; }
        float4 v0 = *(const float4*)(src + off);
        float4 v1 = *(const float4*)(src + off + 4);
        float4 v2 = *(const float4*)(src + off + 8);
        float4 v3 = *(const float4*)(src + off + 12);
        uint4 o0, o1;
        o0.x = packbf(v0.x, v0.y); o0.y = packbf(v0.z, v0.w);
        o0.z = packbf(v1.x, v1.y); o0.w = packbf(v1.z, v1.w);
        o1.x = packbf(v2.x, v2.y); o1.y = packbf(v2.z, v2.w);
        o1.z = packbf(v3.x, v3.y); o1.w = packbf(v3.z, v3.w);
        *(uint4*)(dst + off)     = o0;
        *(uint4*)(dst + off + 8) = o1;
        return;
    }
    // LN part
    int row  = (blockIdx.x - 128) * 8 + (threadIdx.x >> 5);
    int lane = threadIdx.x & 31;
    const float* xr = x + (size_t)row * DD + lane * 8;

    float4 v0 = *(const float4*)(xr);
    float4 v1 = *(const float4*)(xr + 4);
    float d[8] = {v0.x, v0.y, v0.z, v0.w, v1.x, v1.y, v1.z, v1.w};

    float s = d[0]+d[1]+d[2]+d[3]+d[4]+d[5]+d[6]+d[7];
    float mean = warp_sum(s) * (1.0f / DD);

    float ss = 0.f;
    #pragma unroll
    for (int j = 0; j < 8; j++) { d[j] -= mean; ss += d[j] * d[j]; }
    float var = warp_sum(ss) * (1.0f / DD);
    float r = rsqrtf(var + EPS);

    float4 g0 = *(const float4*)(g + lane * 8);
    float4 g1 = *(const float4*)(g + lane * 8 + 4);
    float4 b0 = *(const float4*)(b + lane * 8);
    float4 b1 = *(const float4*)(b + lane * 8 + 4);
    float gg[8] = {g0.x, g0.y, g0.z, g0.w, g1.x, g1.y, g1.z, g1.w};
    float bb2[8] = {b0.x, b0.y, b0.z, b0.w, b1.x, b1.y, b1.z, b1.w};

    float o[8];
    #pragma unroll
    for (int j = 0; j < 8; j++) o[j] = d[j] * r * gg[j] + bb2[j];

    uint4 pk;
    pk.x = packbf(o[0], o[1]);
    pk.y = packbf(o[2], o[3]);
    pk.z = packbf(o[4], o[5]);
    pk.w = packbf(o[6], o[7]);
    *(uint4*)&y[(size_t)row * DD + lane * 8] = pk;
}

// ---------------------------------------------------------------------------
// LayerNorm -> bf16: one WARP per row (8 rows per 256-thread block)
// ---------------------------------------------------------------------------
__global__ __launch_bounds__(256) void ln_kernel(const float* __restrict__ x,
                                                 const float* __restrict__ g,
                                                 const float* __restrict__ b,
                                                 __nv_bfloat16* __restrict__ y) {
    int row  = blockIdx.x * 8 + (threadIdx.x >> 5);
    int lane = threadIdx.x & 31;
    const float* xr = x + (size_t)row * DD + lane * 8;

    float4 v0 = *(const float4*)(xr);
    float4 v1 = *(const float4*)(xr + 4);
    float d[8] = {v0.x, v0.y, v0.z, v0.w, v1.x, v1.y, v1.z, v1.w};

    float s = d[0]+d[1]+d[2]+d[3]+d[4]+d[5]+d[6]+d[7];
    float mean = warp_sum(s) * (1.0f / DD);

    float ss = 0.f;
    #pragma unroll
    for (int j = 0; j < 8; j++) { d[j] -= mean; ss += d[j] * d[j]; }
    float var = warp_sum(ss) * (1.0f / DD);
    float r = rsqrtf(var + EPS);

    float4 g0 = *(const float4*)(g + lane * 8);
    float4 g1 = *(const float4*)(g + lane * 8 + 4);
    float4 b0 = *(const float4*)(b + lane * 8);
    float4 b1 = *(const float4*)(b + lane * 8 + 4);
    float gg[8] = {g0.x, g0.y, g0.z, g0.w, g1.x, g1.y, g1.z, g1.w};
    float bb2[8] = {b0.x, b0.y, b0.z, b0.w, b1.x, b1.y, b1.z, b1.w};

    float o[8];
    #pragma unroll
    for (int j = 0; j < 8; j++) o[j] = d[j] * r * gg[j] + bb2[j];

    uint4 pk;
    pk.x = packbf(o[0], o[1]);
    pk.y = packbf(o[2], o[3]);
    pk.z = packbf(o[4], o[5]);
    pk.w = packbf(o[6], o[7]);
    *(uint4*)&y[(size_t)row * DD + lane * 8] = pk;
}

// ---------------------------------------------------------------------------
// mma helpers
// ---------------------------------------------------------------------------
__device__ __forceinline__ void ldmx4(uint32_t& r0, uint32_t& r1,
                                      uint32_t& r2, uint32_t& r3, uint32_t a) {
    asm volatile("ldmatrix.sync.aligned.m8n8.x4.shared.b16 {%0,%1,%2,%3}, [%4];\n"
                 : "=r"(r0), "=r"(r1), "=r"(r2), "=r"(r3) : "r"(a));
}
__device__ __forceinline__ void ldmx4t(uint32_t& r0, uint32_t& r1,
                                       uint32_t& r2, uint32_t& r3, uint32_t a) {
    asm volatile("ldmatrix.sync.aligned.m8n8.x4.trans.shared.b16 {%0,%1,%2,%3}, [%4];\n"
                 : "=r"(r0), "=r"(r1), "=r"(r2), "=r"(r3) : "r"(a));
}
__device__ __forceinline__ void mma16816(float* c, const uint32_t* a, const uint32_t* b) {
    asm volatile("mma.sync.aligned.m16n8k16.row.col.f32.bf16.bf16.f32 "
                 "{%0,%1,%2,%3}, {%4,%5,%6,%7}, {%8,%9}, {%0,%1,%2,%3};\n"
                 : "+f"(c[0]), "+f"(c[1]), "+f"(c[2]), "+f"(c[3])
                 : "r"(a[0]), "r"(a[1]), "r"(a[2]), "r"(a[3]),
                   "r"(b[0]), "r"(b[1]));
}
__device__ __forceinline__ void mma16816h(float* c, const uint32_t* a, const uint32_t* b) {
    asm volatile("mma.sync.aligned.m16n8k16.row.col.f32.f16.f16.f32 "
                 "{%0,%1,%2,%3}, {%4,%5,%6,%7}, {%8,%9}, {%0,%1,%2,%3};\n"
                 : "+f"(c[0]), "+f"(c[1]), "+f"(c[2]), "+f"(c[3])
                 : "r"(a[0]), "r"(a[1]), "r"(a[2]), "r"(a[3]),
                   "r"(b[0]), "r"(b[1]));
}

// ---------------------------------------------------------------------------
// bf16 tensor-core NT GEMM: 128x64 tile, BK=32, 256 threads,
// 2-stage cp.async pipeline. Warp tile 32x32.
// MODE 1: fp32 out + residual
// MODE 2: silu -> bf16 out
// MODE 3: qkv scatter (Q bf16 pre-scaled by ATT_SC2, K bf16, V fp16)
// ---------------------------------------------------------------------------
template<int MODE>
__global__ __launch_bounds__(256) void gemm_bf(
        const __nv_bfloat16* __restrict__ A,
        const __nv_bfloat16* __restrict__ W,
        const float* __restrict__ bias,
        const float* __restrict__ res,
        float* __restrict__ C,
        __nv_bfloat16* __restrict__ Ob,
        __nv_bfloat16* __restrict__ Kb,
        __half* __restrict__ Vh,
        int M, int K) {
    __shared__ __nv_bfloat16 As[2][128 * PITCH];
    __shared__ __nv_bfloat16 Bs[2][64 * PITCH];

    int t = threadIdx.x, w = t >> 5, lane = t & 31;
    int wm = w >> 1;
    int wn = w & 1;
    int row0 = blockIdx.y * 128;
    int col0 = blockIdx.x * 64;

    uint32_t ab_[2] = { (uint32_t)__cvta_generic_to_shared(As[0]),
                        (uint32_t)__cvta_generic_to_shared(As[1]) };
    uint32_t bb_[2] = { (uint32_t)__cvta_generic_to_shared(Bs[0]),
                        (uint32_t)__cvta_generic_to_shared(Bs[1]) };

    // cp.async indices: A 2 per thread, B 1 per thread
    int ar = t >> 1, ac = (t & 1) * 2;
    int br = t >> 2, bc = t & 3;
    uint32_t soA0 = (uint32_t)(ar * PITCH + ac * 8) * 2;
    uint32_t soA1 = (uint32_t)(ar * PITCH + (ac + 1) * 8) * 2;
    uint32_t soB  = (uint32_t)(br * PITCH + bc * 8) * 2;
    const __nv_bfloat16* asrc = A + (size_t)(row0 + ar) * K;
    const __nv_bfloat16* bsrc = W + (size_t)(col0 + br) * K;

    float c[2][4][4];
    #pragma unroll
    for (int i = 0; i < 2; i++)
        #pragma unroll
        for (int j = 0; j < 4; j++)
            #pragma unroll
            for (int k = 0; k < 4; k++) c[i][j][k] = 0.f;

    // prologue
    cpa16(ab_[0] + soA0, asrc + ac * 8);
    cpa16(ab_[0] + soA1, asrc + (ac + 1) * 8);
    cpa16(bb_[0] + soB,  bsrc + bc * 8);
    asm volatile("cp.async.commit_group;");

    int NK = K >> 5;
    for (int it = 0; it < NK; it++) {
        int cur = it & 1;
        int nb = cur ^ 1;
        if (it + 1 < NK) {
            int k0 = (it + 1) * 32;
            cpa16(ab_[nb] + soA0, asrc + k0 + ac * 8);
            cpa16(ab_[nb] + soA1, asrc + k0 + (ac + 1) * 8);
            cpa16(bb_[nb] + soB,  bsrc + k0 + bc * 8);
            asm volatile("cp.async.commit_group;");
            asm volatile("cp.async.wait_group 1;");
        } else {
            asm volatile("cp.async.wait_group 0;");
        }
        __syncthreads();

        uint32_t abase = ab_[cur], bbase = bb_[cur];
        uint32_t bf[2][2][4];
        #pragma unroll
        for (int nt = 0; nt < 2; nt++) {
            int nrow = wn * 32 + nt * 16 + (lane & 7) + ((lane >> 4) << 3);
            #pragma unroll
            for (int ks = 0; ks < 2; ks++) {
                uint32_t ad = bbase + (uint32_t)(nrow * PITCH + ks * 16 + (lane & 8)) * 2;
                ldmx4(bf[nt][ks][0], bf[nt][ks][1], bf[nt][ks][2], bf[nt][ks][3], ad);
            }
        }
        #pragma unroll
        for (int mt = 0; mt < 2; mt++) {
            int arow = wm * 32 + mt * 16 + (lane & 15);
            #pragma unroll
            for (int ks = 0; ks < 2; ks++) {
                uint32_t af[4];
                uint32_t ad = abase + (uint32_t)(arow * PITCH + ks * 16 + ((lane >> 4) << 3)) * 2;
                ldmx4(af[0], af[1], af[2], af[3], ad);
                #pragma unroll
                for (int nt = 0; nt < 2; nt++) {
                    mma16816(c[mt][2 * nt],     af, &bf[nt][ks][0]);
                    mma16816(c[mt][2 * nt + 1], af, &bf[nt][ks][2]);
                }
            }
        }
        __syncthreads();
    }

    #pragma unroll
    for (int mt = 0; mt < 2; mt++) {
        #pragma unroll
        for (int half = 0; half < 2; half++) {
            int row = row0 + wm * 32 + mt * 16 + (lane >> 2) + half * 8;
            #pragma unroll
            for (int n8 = 0; n8 < 4; n8++) {
                int col = col0 + wn * 32 + n8 * 8 + 2 * (lane & 3);
                float v0 = c[mt][n8][2 * half]     + bias[col];
                float v1 = c[mt][n8][2 * half + 1] + bias[col + 1];
                if (MODE == 1) {
                    const float2 r2 = *(const float2*)&res[(size_t)row * M + col];
                    float2 o; o.x = v0 + r2.x; o.y = v1 + r2.y;
                    *(float2*)&C[(size_t)row * M + col] = o;
                } else if (MODE == 2) {
                    v0 = v0 * (1.0f / (1.0f + __expf(-v0)));
                    v1 = v1 * (1.0f / (1.0f + __expf(-v1)));
                    *(__nv_bfloat162*)&Ob[(size_t)row * M + col] =
                        __floats2bfloat162_rn(v0, v1);
                } else {
                    int seg = col >> 8, rem = col & 255;
                    int h = rem >> 5, d = rem & 31;
                    int b = row >> 11, s = row & 2047;
                    size_t di = ((size_t)(b * HH + h) * SS + s) * DHH + d;
                    if (seg == 0) {
                        *(__nv_bfloat162*)&Ob[di] =
                            __floats2bfloat162_rn(v0 * ATT_SC2, v1 * ATT_SC2);
                    } else if (seg == 1) {
                        *(__nv_bfloat162*)&Kb[di] = __floats2bfloat162_rn(v0, v1);
                    } else {
                        *(__half2*)&Vh[di] = __floats2half2_rn(v0, v1);
                    }
                }
            }
        }
    }
}

// ---------------------------------------------------------------------------
// Split-K tensor-core flash attention.
// S-mma: bf16 (Q pre-scaled). P = ex2.f16x2 of scores. PV-mma: fp16.
// grid (BH=32, S/128=16, KSPLIT=2), block 128 (4 warps; warp owns 32 q rows).
// K/V tiles: 3-stage cp.async ring, ONE __syncthreads per iteration.
// Writes UNNORMALIZED partial O (fp32) and partial l.
// ---------------------------------------------------------------------------
__global__ __launch_bounds__(128) void attn_mma(const __nv_bfloat16* __restrict__ Qb,
                                                const __nv_bfloat16* __restrict__ Kb,
                                                const __half* __restrict__ Vh,
                                                float* __restrict__ po,
                                                float* __restrict__ pl) {
    __shared__ __nv_bfloat16 Qs[128 * PITCH];
    __shared__ __nv_bfloat16 Ks[3][64 * PITCH];
    __shared__ __half        Vs[3][64 * PITCH];

    int bh = blockIdx.x;
    int qt = blockIdx.y;
    int z  = blockIdx.z;
    int t = threadIdx.x, w = t >> 5, lane = t & 31;

    const __nv_bfloat16* qsrc = Qb + ((size_t)bh * SS + qt * 128) * DHH;
    const __nv_bfloat16* ksrc = Kb + ((size_t)bh * SS + z * KSEG) * DHH;
    const __half*        vsrc = Vh + ((size_t)bh * SS + z * KSEG) * DHH;

    uint32_t qbase = (uint32_t)__cvta_generic_to_shared(Qs);
    uint32_t kb_[3] = { (uint32_t)__cvta_generic_to_shared(Ks[0]),
                        (uint32_t)__cvta_generic_to_shared(Ks[1]),
                        (uint32_t)__cvta_generic_to_shared(Ks[2]) };
    uint32_t vb_[3] = { (uint32_t)__cvta_generic_to_shared(Vs[0]),
                        (uint32_t)__cvta_generic_to_shared(Vs[1]),
                        (uint32_t)__cvta_generic_to_shared(Vs[2]) };

    #pragma unroll
    for (int i = t; i < 512; i += 128) {
        int r = i >> 2, s = i & 3;
        *(uint4*)&Qs[r * PITCH + s * 8] = *(const uint4*)&qsrc[r * 32 + s * 8];
    }

    int lr = t >> 2, ls = t & 3;
    uint32_t so0 = (uint32_t)(lr * PITCH + ls * 8) * 2;
    uint32_t so1 = (uint32_t)((lr + 32) * PITCH + ls * 8) * 2;

    // prologue: stage 0 and stage 1 (two commit groups)
    cpa16(kb_[0] + so0, &ksrc[lr * 32 + ls * 8]);
    cpa16(kb_[0] + so1, &ksrc[(lr + 32) * 32 + ls * 8]);
    cpa16(vb_[0] + so0, &vsrc[lr * 32 + ls * 8]);
    cpa16(vb_[0] + so1, &vsrc[(lr + 32) * 32 + ls * 8]);
    asm volatile("cp.async.commit_group;");
    cpa16(kb_[1] + so0, &ksrc[(64 + lr) * 32 + ls * 8]);
    cpa16(kb_[1] + so1, &ksrc[(64 + lr + 32) * 32 + ls * 8]);
    cpa16(vb_[1] + so0, &vsrc[(64 + lr) * 32 + ls * 8]);
    cpa16(vb_[1] + so1, &vsrc[(64 + lr + 32) * 32 + ls * 8]);
    asm volatile("cp.async.commit_group;");

    __syncthreads();   // Q ready

    uint32_t qa[2][2][4];
    #pragma unroll
    for (int mt = 0; mt < 2; mt++) {
        int row = w * 32 + mt * 16 + (lane & 15);
        #pragma unroll
        for (int ks = 0; ks < 2; ks++) {
            uint32_t a = qbase + (uint32_t)(row * PITCH + ks * 16 + ((lane >> 4) << 3)) * 2;
            ldmx4(qa[mt][ks][0], qa[mt][ks][1], qa[mt][ks][2], qa[mt][ks][3], a);
        }
    }

    float O[2][4][4];
    #pragma unroll
    for (int mt = 0; mt < 2; mt++)
        #pragma unroll
        for (int i = 0; i < 4; i++)
            #pragma unroll
            for (int j = 0; j < 4; j++) O[mt][i][j] = 0.f;
    float Oext[2][4] = {{0.f,0.f,0.f,0.f},{0.f,0.f,0.f,0.f}};
    const uint32_t onesh[2] = {0x3C003C00u, 0x3C003C00u};   // f16 1.0 x2

    const int NIT = KSEG / 64;   // 16
    for (int it = 0; it < NIT; it++) {
        if (it + 1 < NIT) {
            asm volatile("cp.async.wait_group 1;");
        } else {
            asm volatile("cp.async.wait_group 0;");
        }
        __syncthreads();   // single barrier: data visible + prior stage readers done

        // prefetch stage it+2 into ring slot (it+2)%3
        if (it + 2 < NIT) {
            int st = (it + 2) % 3;
            int koff = (it + 2) * 64;
            cpa16(kb_[st] + so0, &ksrc[(koff + lr) * 32 + ls * 8]);
            cpa16(kb_[st] + so1, &ksrc[(koff + lr + 32) * 32 + ls * 8]);
            cpa16(vb_[st] + so0, &vsrc[(koff + lr) * 32 + ls * 8]);
            cpa16(vb_[st] + so1, &vsrc[(koff + lr + 32) * 32 + ls * 8]);
            asm volatile("cp.async.commit_group;");
        }

        int cur = it % 3;
        uint32_t kba = kb_[cur], vba = vb_[cur];
        #pragma unroll
        for (int j = 0; j < 4; j++) {            // 16-key slabs
            uint32_t b0[4], b1[4];
            int nrow = j * 16 + (lane & 7) + ((lane >> 4) << 3);
            ldmx4(b0[0], b0[1], b0[2], b0[3],
                  kba + (uint32_t)(nrow * PITCH + (lane & 8)) * 2);
            ldmx4(b1[0], b1[1], b1[2], b1[3],
                  kba + (uint32_t)(nrow * PITCH + 16 + (lane & 8)) * 2);

            float c[2][2][4];
            #pragma unroll
            for (int mt = 0; mt < 2; mt++) {
                #pragma unroll
                for (int i = 0; i < 4; i++) { c[mt][0][i] = 0.f; c[mt][1][i] = 0.f; }
                mma16816(c[mt][0], qa[mt][0], &b0[0]);
                mma16816(c[mt][0], qa[mt][1], &b1[0]);
                mma16816(c[mt][1], qa[mt][0], &b0[2]);
                mma16816(c[mt][1], qa[mt][1], &b1[2]);
            }

            // P = 2^score; one MUFU per 2 scores
            uint32_t pa[2][4];
            #pragma unroll
            for (int mt = 0; mt < 2; mt++) {
                pa[mt][0] = exp2h2(c[mt][0][0], c[mt][0][1]);
                pa[mt][1] = exp2h2(c[mt][0][2], c[mt][0][3]);
                pa[mt][2] = exp2h2(c[mt][1][0], c[mt][1][1]);
                pa[mt][3] = exp2h2(c[mt][1][2], c[mt][1][3]);
                mma16816h(Oext[mt], pa[mt], onesh);
            }

            int vrow = j * 16 + (lane & 15);
            uint32_t v0[4], v1[4];
            ldmx4t(v0[0], v0[1], v0[2], v0[3],
                   vba + (uint32_t)(vrow * PITCH + ((lane >> 4) << 3)) * 2);
            ldmx4t(v1[0], v1[1], v1[2], v1[3],
                   vba + (uint32_t)(vrow * PITCH + 16 + ((lane >> 4) << 3)) * 2);

            #pragma unroll
            for (int mt = 0; mt < 2; mt++) {
                mma16816h(O[mt][0], pa[mt], &v0[0]);
                mma16816h(O[mt][1], pa[mt], &v0[2]);
                mma16816h(O[mt][2], pa[mt], &v1[0]);
                mma16816h(O[mt][3], pa[mt], &v1[2]);
            }
        }
    }

    int b = bh >> 3, h = bh & 7;
    float* poz = po + (size_t)z * NTOK * DD;
    float* plz = pl + (size_t)z * NTOK * HH;
    #pragma unroll
    for (int mt = 0; mt < 2; mt++) {
        int r0 = qt * 128 + w * 32 + mt * 16 + (lane >> 2);
        int n  = b * SS + r0;
        size_t base = (size_t)n * DD + h * DHH;
        if ((lane & 3) == 0) {
            plz[(size_t)n * HH + h]       = Oext[mt][0];
            plz[(size_t)(n + 8) * HH + h] = Oext[mt][2];
        }
        #pragma unroll
        for (int nt = 0; nt < 4; nt++) {
            int colo = nt * 8 + 2 * (lane & 3);
            float2 u0; u0.x = O[mt][nt][0]; u0.y = O[mt][nt][1];
            *(float2*)&poz[base + colo] = u0;
            float2 u1; u1.x = O[mt][nt][2]; u1.y = O[mt][nt][3];
            *(float2*)&poz[base + 8 * DD + colo] = u1;
        }
    }
}

// ---------------------------------------------------------------------------
// Split-K combine: ctx = (O0 + O1) / (l0 + l1), packed bf16. Pure streaming.
// ---------------------------------------------------------------------------
__global__ __launch_bounds__(256) void attn_combine(const float* __restrict__ po,
                                                    const float* __restrict__ pl,
                                                    __nv_bfloat16* __restrict__ ctx) {
    int i = blockIdx.x * 256 + threadIdx.x;    // 0 .. NTOK*DD/8 - 1
    size_t e = (size_t)i * 8;
    int n = (int)(e >> 8);                     // token
    int col = (int)(e & 255);
    int h = col >> 5;

    float l = pl[(size_t)n * HH + h] + pl[(size_t)NTOK * HH + (size_t)n * HH + h];
    float inv = 1.0f / l;

    float4 a0 = *(const float4*)&po[e];
    float4 a1 = *(const float4*)&po[e + 4];
    float4 b0 = *(const float4*)&po[(size_t)NTOK * DD + e];
    float4 b1 = *(const float4*)&po[(size_t)NTOK * DD + e + 4];

    uint4 pk;
    pk.x = packbf((a0.x + b0.x) * inv, (a0.y + b0.y) * inv);
    pk.y = packbf((a0.z + b0.z) * inv, (a0.w + b0.w) * inv);
    pk.z = packbf((a1.x + b1.x) * inv, (a1.y + b1.y) * inv);
    pk.w = packbf((a1.z + b1.z) * inv, (a1.w + b1.w) * inv);
    *(uint4*)&ctx[e] = pk;
}

// ---------------------------------------------------------------------------
// Launch
// ---------------------------------------------------------------------------
extern "C" void kernel_launch(void* const* d_in, const int* in_sizes, int n_in,
                              void* d_out, int out_size) {
    const float* x      = (const float*)d_in[0];
    const float* ln1_g  = (const float*)d_in[1];
    const float* ln1_b  = (const float*)d_in[2];
    const float* w_qkv  = (const float*)d_in[3];
    const float* b_qkv  = (const float*)d_in[4];
    const float* w_proj = (const float*)d_in[5];
    const float* b_proj = (const float*)d_in[6];
    const float* ln2_g  = (const float*)d_in[7];
    const float* ln2_b  = (const float*)d_in[8];
    const float* w1     = (const float*)d_in[9];
    const float* b1     = (const float*)d_in[10];
    const float* w2     = (const float*)d_in[11];
    const float* b2     = (const float*)d_in[12];
    float* out = (float*)d_out;

    __nv_bfloat16 *yb, *ctxb, *hb, *qb, *kb, *wqkvb, *wprojb, *w1b, *w2b;
    __half *vh;
    float *x1, *po, *pl;
    cudaGetSymbolAddress((void**)&yb,     g_yb);
    cudaGetSymbolAddress((void**)&ctxb,   g_ctxb);
    cudaGetSymbolAddress((void**)&x1,     g_x1);
    cudaGetSymbolAddress((void**)&hb,     g_hb);
    cudaGetSymbolAddress((void**)&qb,     g_qb);
    cudaGetSymbolAddress((void**)&kb,     g_kb);
    cudaGetSymbolAddress((void**)&vh,     g_vh);
    cudaGetSymbolAddress((void**)&wqkvb,  g_wqkvb);
    cudaGetSymbolAddress((void**)&wprojb, g_wprojb);
    cudaGetSymbolAddress((void**)&w1b,    g_w1b);
    cudaGetSymbolAddress((void**)&w2b,    g_w2b);
    cudaGetSymbolAddress((void**)&po,     g_po);
    cudaGetSymbolAddress((void**)&pl,     g_pl);

    // 0+1. fused weight conversion + LN1 (one launch)
    f2bf_ln<<<128 + NTOK/8, 256>>>(w_qkv, w_proj, w1, w2,
                                   wqkvb, wprojb, w1b, w2b,
                                   x, ln1_g, ln1_b, yb);
    // 2. QKV GEMM -> Q bf16 (pre-scaled) / K bf16 / V fp16
    gemm_bf<3><<<dim3(768/64, NTOK/128), 256>>>(yb, wqkvb, b_qkv, nullptr, nullptr,
                                                qb, kb, vh, 3*DD, DD);
    // 3. split-K attention -> partial O/l, then streaming combine -> ctx bf16
    attn_mma<<<dim3(BB*HH, SS/128, KSPLIT), 128>>>(qb, kb, vh, po, pl);
    attn_combine<<<NTOK*DD/8/256, 256>>>(po, pl, ctxb);
    // 4. proj + residual -> x1 fp32 (plain GEMM)
    gemm_bf<1><<<dim3(DD/64, NTOK/128), 256>>>(ctxb, wprojb, b_proj, x, x1,
                                               nullptr, nullptr, nullptr, DD, DD);
    // 5. LN2 -> bf16
    ln_kernel<<<NTOK/8, 256>>>(x1, ln2_g, ln2_b, yb);
    // 6. FFN1 + silu -> bf16 h
    gemm_bf<2><<<dim3(DFF/64, NTOK/128), 256>>>(yb, w1b, b1, nullptr, nullptr,
                                                hb, nullptr, nullptr, DFF, DD);
    // 7. FFN2 + residual -> out fp32
    gemm_bf<1><<<dim3(DD/64, NTOK/128), 256>>>(hb, w2b, b2, x1, out,
                                               nullptr, nullptr, nullptr, DD, DFF);
}

// round 17
// speedup vs baseline: 1.1350x; 1.0065x over previous
#include <cuda_runtime.h>
#include <cuda_bf16.h>
#include <cuda_fp16.h>
#include <cstdint>

// Problem constants
#define BB    4
#define SS    2048
#define DD    256
#define HH    8
#define DHH   32
#define DFF   512
#define NTOK  (BB*SS)          // 8192
#define EPS   1e-5f
// softmax scale * log2(e), folded into Q at QKV epilogue
#define ATT_SC2 0.25503540f
#define KSPLIT 2
#define KSEG   (SS/KSPLIT)     // 1024

// smem row pitch in halves (80B): conflict-free + 16B-aligned rows for ldmatrix
#define PITCH 40

// ---------------------------------------------------------------------------
// Scratch (device globals; no allocations allowed)
// ---------------------------------------------------------------------------
__device__ __nv_bfloat16 g_yb [NTOK * DD];        // LN output (bf16)
__device__ __nv_bfloat16 g_ctxb[NTOK * DD];       // combined attention ctx (bf16)
__device__ float         g_x1 [NTOK * DD];        // residual after attention
__device__ __nv_bfloat16 g_hb [NTOK * DFF];       // FFN hidden (bf16)
__device__ __nv_bfloat16 g_qb[BB*HH * SS * DHH];  // Q bf16 (pre-scaled) [bh][s][32]
__device__ __nv_bfloat16 g_kb[BB*HH * SS * DHH];  // K bf16
__device__ __half        g_vh[BB*HH * SS * DHH];  // V fp16
__device__ __nv_bfloat16 g_wqkvb[3*DD * DD];      // bf16 weights
__device__ __nv_bfloat16 g_wprojb[DD * DD];
__device__ __nv_bfloat16 g_w1b[DFF * DD];
__device__ __nv_bfloat16 g_w2b[DD * DFF];
__device__ __half g_po[KSPLIT * NTOK * DD];       // split-K partial O (fp16)
__device__ float  g_pl[KSPLIT * NTOK * HH];       // split-K partial l

__device__ __forceinline__ uint32_t packbf(float lo, float hi) {
    __nv_bfloat162 t = __floats2bfloat162_rn(lo, hi);
    return *reinterpret_cast<uint32_t*>(&t);
}
// pack 2 fp32 exponent args -> f16x2, then 2^x on both halves (1 MUFU op)
__device__ __forceinline__ uint32_t exp2h2(float lo, float hi) {
    uint32_t d;
    asm("cvt.rn.f16x2.f32 %0, %1, %2;" : "=r"(d) : "f"(hi), "f"(lo));
    asm("ex2.approx.f16x2 %0, %0;" : "+r"(d));
    return d;
}
__device__ __forceinline__ void cpa16(uint32_t dst, const void* src) {
    asm volatile("cp.async.cg.shared.global [%0], [%1], 16;" :: "r"(dst), "l"(src));
}

__device__ __forceinline__ float warp_sum(float v) {
    #pragma unroll
    for (int o = 16; o > 0; o >>= 1) v += __shfl_xor_sync(0xffffffffu, v, o);
    return v;
}

// ---------------------------------------------------------------------------
// Fused: weight fp32->bf16 conversion (blocks 0..127) + LayerNorm1 (rest).
// ---------------------------------------------------------------------------
__global__ __launch_bounds__(256) void f2bf_ln(
        const float* __restrict__ s0, const float* __restrict__ s1,
        const float* __restrict__ s2, const float* __restrict__ s3,
        __nv_bfloat16* __restrict__ d0, __nv_bfloat16* __restrict__ d1,
        __nv_bfloat16* __restrict__ d2, __nv_bfloat16* __restrict__ d3,
        const float* __restrict__ x, const float* __restrict__ g,
        const float* __restrict__ b, __nv_bfloat16* __restrict__ y) {
    if (blockIdx.x < 128) {
        int i = blockIdx.x * 256 + threadIdx.x;     // 0..32767
        int idx = i * 16;
        const float* src; __nv_bfloat16* dst; int off;
        if (idx < 196608)      { src = s0; dst = d0; off = idx; }
        else if (idx < 262144) { src = s1; dst = d1; off = idx - 196608; }
        else if (idx < 393216) { src = s2; dst = d2; off = idx - 262144; }
        else                   { src = s3; dst = d3; off = idx - 393216; }
        float4 v0 = *(const float4*)(src + off);
        float4 v1 = *(const float4*)(src + off + 4);
        float4 v2 = *(const float4*)(src + off + 8);
        float4 v3 = *(const float4*)(src + off + 12);
        uint4 o0, o1;
        o0.x = packbf(v0.x, v0.y); o0.y = packbf(v0.z, v0.w);
        o0.z = packbf(v1.x, v1.y); o0.w = packbf(v1.z, v1.w);
        o1.x = packbf(v2.x, v2.y); o1.y = packbf(v2.z, v2.w);
        o1.z = packbf(v3.x, v3.y); o1.w = packbf(v3.z, v3.w);
        *(uint4*)(dst + off)     = o0;
        *(uint4*)(dst + off + 8) = o1;
        return;
    }
    // LN part
    int row  = (blockIdx.x - 128) * 8 + (threadIdx.x >> 5);
    int lane = threadIdx.x & 31;
    const float* xr = x + (size_t)row * DD + lane * 8;

    float4 v0 = *(const float4*)(xr);
    float4 v1 = *(const float4*)(xr + 4);
    float d[8] = {v0.x, v0.y, v0.z, v0.w, v1.x, v1.y, v1.z, v1.w};

    float s = d[0]+d[1]+d[2]+d[3]+d[4]+d[5]+d[6]+d[7];
    float mean = warp_sum(s) * (1.0f / DD);

    float ss = 0.f;
    #pragma unroll
    for (int j = 0; j < 8; j++) { d[j] -= mean; ss += d[j] * d[j]; }
    float var = warp_sum(ss) * (1.0f / DD);
    float r = rsqrtf(var + EPS);

    float4 g0 = *(const float4*)(g + lane * 8);
    float4 g1 = *(const float4*)(g + lane * 8 + 4);
    float4 b0 = *(const float4*)(b + lane * 8);
    float4 b1 = *(const float4*)(b + lane * 8 + 4);
    float gg[8] = {g0.x, g0.y, g0.z, g0.w, g1.x, g1.y, g1.z, g1.w};
    float bb2[8] = {b0.x, b0.y, b0.z, b0.w, b1.x, b1.y, b1.z, b1.w};

    float o[8];
    #pragma unroll
    for (int j = 0; j < 8; j++) o[j] = d[j] * r * gg[j] + bb2[j];

    uint4 pk;
    pk.x = packbf(o[0], o[1]);
    pk.y = packbf(o[2], o[3]);
    pk.z = packbf(o[4], o[5]);
    pk.w = packbf(o[6], o[7]);
    *(uint4*)&y[(size_t)row * DD + lane * 8] = pk;
}

// ---------------------------------------------------------------------------
// LayerNorm -> bf16: one WARP per row (8 rows per 256-thread block)
// ---------------------------------------------------------------------------
__global__ __launch_bounds__(256) void ln_kernel(const float* __restrict__ x,
                                                 const float* __restrict__ g,
                                                 const float* __restrict__ b,
                                                 __nv_bfloat16* __restrict__ y) {
    int row  = blockIdx.x * 8 + (threadIdx.x >> 5);
    int lane = threadIdx.x & 31;
    const float* xr = x + (size_t)row * DD + lane * 8;

    float4 v0 = *(const float4*)(xr);
    float4 v1 = *(const float4*)(xr + 4);
    float d[8] = {v0.x, v0.y, v0.z, v0.w, v1.x, v1.y, v1.z, v1.w};

    float s = d[0]+d[1]+d[2]+d[3]+d[4]+d[5]+d[6]+d[7];
    float mean = warp_sum(s) * (1.0f / DD);

    float ss = 0.f;
    #pragma unroll
    for (int j = 0; j < 8; j++) { d[j] -= mean; ss += d[j] * d[j]; }
    float var = warp_sum(ss) * (1.0f / DD);
    float r = rsqrtf(var + EPS);

    float4 g0 = *(const float4*)(g + lane * 8);
    float4 g1 = *(const float4*)(g + lane * 8 + 4);
    float4 b0 = *(const float4*)(b + lane * 8);
    float4 b1 = *(const float4*)(b + lane * 8 + 4);
    float gg[8] = {g0.x, g0.y, g0.z, g0.w, g1.x, g1.y, g1.z, g1.w};
    float bb2[8] = {b0.x, b0.y, b0.z, b0.w, b1.x, b1.y, b1.z, b1.w};

    float o[8];
    #pragma unroll
    for (int j = 0; j < 8; j++) o[j] = d[j] * r * gg[j] + bb2[j];

    uint4 pk;
    pk.x = packbf(o[0], o[1]);
    pk.y = packbf(o[2], o[3]);
    pk.z = packbf(o[4], o[5]);
    pk.w = packbf(o[6], o[7]);
    *(uint4*)&y[(size_t)row * DD + lane * 8] = pk;
}

// ---------------------------------------------------------------------------
// mma helpers
// ---------------------------------------------------------------------------
__device__ __forceinline__ void ldmx4(uint32_t& r0, uint32_t& r1,
                                      uint32_t& r2, uint32_t& r3, uint32_t a) {
    asm volatile("ldmatrix.sync.aligned.m8n8.x4.shared.b16 {%0,%1,%2,%3}, [%4];\n"
                 : "=r"(r0), "=r"(r1), "=r"(r2), "=r"(r3) : "r"(a));
}
__device__ __forceinline__ void ldmx4t(uint32_t& r0, uint32_t& r1,
                                       uint32_t& r2, uint32_t& r3, uint32_t a) {
    asm volatile("ldmatrix.sync.aligned.m8n8.x4.trans.shared.b16 {%0,%1,%2,%3}, [%4];\n"
                 : "=r"(r0), "=r"(r1), "=r"(r2), "=r"(r3) : "r"(a));
}
__device__ __forceinline__ void mma16816(float* c, const uint32_t* a, const uint32_t* b) {
    asm volatile("mma.sync.aligned.m16n8k16.row.col.f32.bf16.bf16.f32 "
                 "{%0,%1,%2,%3}, {%4,%5,%6,%7}, {%8,%9}, {%0,%1,%2,%3};\n"
                 : "+f"(c[0]), "+f"(c[1]), "+f"(c[2]), "+f"(c[3])
                 : "r"(a[0]), "r"(a[1]), "r"(a[2]), "r"(a[3]),
                   "r"(b[0]), "r"(b[1]));
}
__device__ __forceinline__ void mma16816h(float* c, const uint32_t* a, const uint32_t* b) {
    asm volatile("mma.sync.aligned.m16n8k16.row.col.f32.f16.f16.f32 "
                 "{%0,%1,%2,%3}, {%4,%5,%6,%7}, {%8,%9}, {%0,%1,%2,%3};\n"
                 : "+f"(c[0]), "+f"(c[1]), "+f"(c[2]), "+f"(c[3])
                 : "r"(a[0]), "r"(a[1]), "r"(a[2]), "r"(a[3]),
                   "r"(b[0]), "r"(b[1]));
}

// ---------------------------------------------------------------------------
// bf16 tensor-core NT GEMM: 128x64 tile, BK=32, 256 threads,
// 2-stage cp.async pipeline. Warp tile 32x32.
// MODE 1: fp32 out + residual
// MODE 2: silu -> bf16 out
// MODE 3: qkv scatter (Q bf16 pre-scaled by ATT_SC2, K bf16, V fp16)
// ---------------------------------------------------------------------------
template<int MODE>
__global__ __launch_bounds__(256) void gemm_bf(
        const __nv_bfloat16* __restrict__ A,
        const __nv_bfloat16* __restrict__ W,
        const float* __restrict__ bias,
        const float* __restrict__ res,
        float* __restrict__ C,
        __nv_bfloat16* __restrict__ Ob,
        __nv_bfloat16* __restrict__ Kb,
        __half* __restrict__ Vh,
        int M, int K) {
    __shared__ __nv_bfloat16 As[2][128 * PITCH];
    __shared__ __nv_bfloat16 Bs[2][64 * PITCH];

    int t = threadIdx.x, w = t >> 5, lane = t & 31;
    int wm = w >> 1;
    int wn = w & 1;
    int row0 = blockIdx.y * 128;
    int col0 = blockIdx.x * 64;

    uint32_t ab_[2] = { (uint32_t)__cvta_generic_to_shared(As[0]),
                        (uint32_t)__cvta_generic_to_shared(As[1]) };
    uint32_t bb_[2] = { (uint32_t)__cvta_generic_to_shared(Bs[0]),
                        (uint32_t)__cvta_generic_to_shared(Bs[1]) };

    // cp.async indices: A 2 per thread, B 1 per thread
    int ar = t >> 1, ac = (t & 1) * 2;
    int br = t >> 2, bc = t & 3;
    uint32_t soA0 = (uint32_t)(ar * PITCH + ac * 8) * 2;
    uint32_t soA1 = (uint32_t)(ar * PITCH + (ac + 1) * 8) * 2;
    uint32_t soB  = (uint32_t)(br * PITCH + bc * 8) * 2;
    const __nv_bfloat16* asrc = A + (size_t)(row0 + ar) * K;
    const __nv_bfloat16* bsrc = W + (size_t)(col0 + br) * K;

    float c[2][4][4];
    #pragma unroll
    for (int i = 0; i < 2; i++)
        #pragma unroll
        for (int j = 0; j < 4; j++)
            #pragma unroll
            for (int k = 0; k < 4; k++) c[i][j][k] = 0.f;

    // prologue
    cpa16(ab_[0] + soA0, asrc + ac * 8);
    cpa16(ab_[0] + soA1, asrc + (ac + 1) * 8);
    cpa16(bb_[0] + soB,  bsrc + bc * 8);
    asm volatile("cp.async.commit_group;");

    int NK = K >> 5;
    for (int it = 0; it < NK; it++) {
        int cur = it & 1;
        int nb = cur ^ 1;
        if (it + 1 < NK) {
            int k0 = (it + 1) * 32;
            cpa16(ab_[nb] + soA0, asrc + k0 + ac * 8);
            cpa16(ab_[nb] + soA1, asrc + k0 + (ac + 1) * 8);
            cpa16(bb_[nb] + soB,  bsrc + k0 + bc * 8);
            asm volatile("cp.async.commit_group;");
            asm volatile("cp.async.wait_group 1;");
        } else {
            asm volatile("cp.async.wait_group 0;");
        }
        __syncthreads();

        uint32_t abase = ab_[cur], bbase = bb_[cur];
        uint32_t bf[2][2][4];
        #pragma unroll
        for (int nt = 0; nt < 2; nt++) {
            int nrow = wn * 32 + nt * 16 + (lane & 7) + ((lane >> 4) << 3);
            #pragma unroll
            for (int ks = 0; ks < 2; ks++) {
                uint32_t ad = bbase + (uint32_t)(nrow * PITCH + ks * 16 + (lane & 8)) * 2;
                ldmx4(bf[nt][ks][0], bf[nt][ks][1], bf[nt][ks][2], bf[nt][ks][3], ad);
            }
        }
        #pragma unroll
        for (int mt = 0; mt < 2; mt++) {
            int arow = wm * 32 + mt * 16 + (lane & 15);
            #pragma unroll
            for (int ks = 0; ks < 2; ks++) {
                uint32_t af[4];
                uint32_t ad = abase + (uint32_t)(arow * PITCH + ks * 16 + ((lane >> 4) << 3)) * 2;
                ldmx4(af[0], af[1], af[2], af[3], ad);
                #pragma unroll
                for (int nt = 0; nt < 2; nt++) {
                    mma16816(c[mt][2 * nt],     af, &bf[nt][ks][0]);
                    mma16816(c[mt][2 * nt + 1], af, &bf[nt][ks][2]);
                }
            }
        }
        __syncthreads();
    }

    #pragma unroll
    for (int mt = 0; mt < 2; mt++) {
        #pragma unroll
        for (int half = 0; half < 2; half++) {
            int row = row0 + wm * 32 + mt * 16 + (lane >> 2) + half * 8;
            #pragma unroll
            for (int n8 = 0; n8 < 4; n8++) {
                int col = col0 + wn * 32 + n8 * 8 + 2 * (lane & 3);
                float v0 = c[mt][n8][2 * half]     + bias[col];
                float v1 = c[mt][n8][2 * half + 1] + bias[col + 1];
                if (MODE == 1) {
                    const float2 r2 = *(const float2*)&res[(size_t)row * M + col];
                    float2 o; o.x = v0 + r2.x; o.y = v1 + r2.y;
                    *(float2*)&C[(size_t)row * M + col] = o;
                } else if (MODE == 2) {
                    v0 = v0 * (1.0f / (1.0f + __expf(-v0)));
                    v1 = v1 * (1.0f / (1.0f + __expf(-v1)));
                    *(__nv_bfloat162*)&Ob[(size_t)row * M + col] =
                        __floats2bfloat162_rn(v0, v1);
                } else {
                    int seg = col >> 8, rem = col & 255;
                    int h = rem >> 5, d = rem & 31;
                    int b = row >> 11, s = row & 2047;
                    size_t di = ((size_t)(b * HH + h) * SS + s) * DHH + d;
                    if (seg == 0) {
                        *(__nv_bfloat162*)&Ob[di] =
                            __floats2bfloat162_rn(v0 * ATT_SC2, v1 * ATT_SC2);
                    } else if (seg == 1) {
                        *(__nv_bfloat162*)&Kb[di] = __floats2bfloat162_rn(v0, v1);
                    } else {
                        *(__half2*)&Vh[di] = __floats2half2_rn(v0, v1);
                    }
                }
            }
        }
    }
}

// ---------------------------------------------------------------------------
// Split-K tensor-core flash attention.
// S-mma: bf16 (Q pre-scaled). P = ex2.f16x2 of scores. PV-mma: fp16.
// grid (BH=32, S/128=16, KSPLIT=2), block 128 (4 warps; warp owns 32 q rows).
// K/V tiles: 3-stage cp.async ring, ONE __syncthreads per iteration.
// Writes UNNORMALIZED partial O (fp16) and partial l (fp32).
// ---------------------------------------------------------------------------
__global__ __launch_bounds__(128) void attn_mma(const __nv_bfloat16* __restrict__ Qb,
                                                const __nv_bfloat16* __restrict__ Kb,
                                                const __half* __restrict__ Vh,
                                                __half* __restrict__ po,
                                                float* __restrict__ pl) {
    __shared__ __nv_bfloat16 Qs[128 * PITCH];
    __shared__ __nv_bfloat16 Ks[3][64 * PITCH];
    __shared__ __half        Vs[3][64 * PITCH];

    int bh = blockIdx.x;
    int qt = blockIdx.y;
    int z  = blockIdx.z;
    int t = threadIdx.x, w = t >> 5, lane = t & 31;

    const __nv_bfloat16* qsrc = Qb + ((size_t)bh * SS + qt * 128) * DHH;
    const __nv_bfloat16* ksrc = Kb + ((size_t)bh * SS + z * KSEG) * DHH;
    const __half*        vsrc = Vh + ((size_t)bh * SS + z * KSEG) * DHH;

    uint32_t qbase = (uint32_t)__cvta_generic_to_shared(Qs);
    uint32_t kb_[3] = { (uint32_t)__cvta_generic_to_shared(Ks[0]),
                        (uint32_t)__cvta_generic_to_shared(Ks[1]),
                        (uint32_t)__cvta_generic_to_shared(Ks[2]) };
    uint32_t vb_[3] = { (uint32_t)__cvta_generic_to_shared(Vs[0]),
                        (uint32_t)__cvta_generic_to_shared(Vs[1]),
                        (uint32_t)__cvta_generic_to_shared(Vs[2]) };

    #pragma unroll
    for (int i = t; i < 512; i += 128) {
        int r = i >> 2, s = i & 3;
        *(uint4*)&Qs[r * PITCH + s * 8] = *(const uint4*)&qsrc[r * 32 + s * 8];
    }

    int lr = t >> 2, ls = t & 3;
    uint32_t so0 = (uint32_t)(lr * PITCH + ls * 8) * 2;
    uint32_t so1 = (uint32_t)((lr + 32) * PITCH + ls * 8) * 2;

    // prologue: stage 0 and stage 1 (two commit groups)
    cpa16(kb_[0] + so0, &ksrc[lr * 32 + ls * 8]);
    cpa16(kb_[0] + so1, &ksrc[(lr + 32) * 32 + ls * 8]);
    cpa16(vb_[0] + so0, &vsrc[lr * 32 + ls * 8]);
    cpa16(vb_[0] + so1, &vsrc[(lr + 32) * 32 + ls * 8]);
    asm volatile("cp.async.commit_group;");
    cpa16(kb_[1] + so0, &ksrc[(64 + lr) * 32 + ls * 8]);
    cpa16(kb_[1] + so1, &ksrc[(64 + lr + 32) * 32 + ls * 8]);
    cpa16(vb_[1] + so0, &vsrc[(64 + lr) * 32 + ls * 8]);
    cpa16(vb_[1] + so1, &vsrc[(64 + lr + 32) * 32 + ls * 8]);
    asm volatile("cp.async.commit_group;");

    __syncthreads();   // Q ready

    uint32_t qa[2][2][4];
    #pragma unroll
    for (int mt = 0; mt < 2; mt++) {
        int row = w * 32 + mt * 16 + (lane & 15);
        #pragma unroll
        for (int ks = 0; ks < 2; ks++) {
            uint32_t a = qbase + (uint32_t)(row * PITCH + ks * 16 + ((lane >> 4) << 3)) * 2;
            ldmx4(qa[mt][ks][0], qa[mt][ks][1], qa[mt][ks][2], qa[mt][ks][3], a);
        }
    }

    float O[2][4][4];
    #pragma unroll
    for (int mt = 0; mt < 2; mt++)
        #pragma unroll
        for (int i = 0; i < 4; i++)
            #pragma unroll
            for (int j = 0; j < 4; j++) O[mt][i][j] = 0.f;
    float Oext[2][4] = {{0.f,0.f,0.f,0.f},{0.f,0.f,0.f,0.f}};
    const uint32_t onesh[2] = {0x3C003C00u, 0x3C003C00u};   // f16 1.0 x2

    const int NIT = KSEG / 64;   // 16
    for (int it = 0; it < NIT; it++) {
        if (it + 1 < NIT) {
            asm volatile("cp.async.wait_group 1;");
        } else {
            asm volatile("cp.async.wait_group 0;");
        }
        __syncthreads();   // single barrier: data visible + prior stage readers done

        // prefetch stage it+2 into ring slot (it+2)%3
        if (it + 2 < NIT) {
            int st = (it + 2) % 3;
            int koff = (it + 2) * 64;
            cpa16(kb_[st] + so0, &ksrc[(koff + lr) * 32 + ls * 8]);
            cpa16(kb_[st] + so1, &ksrc[(koff + lr + 32) * 32 + ls * 8]);
            cpa16(vb_[st] + so0, &vsrc[(koff + lr) * 32 + ls * 8]);
            cpa16(vb_[st] + so1, &vsrc[(koff + lr + 32) * 32 + ls * 8]);
            asm volatile("cp.async.commit_group;");
        }

        int cur = it % 3;
        uint32_t kba = kb_[cur], vba = vb_[cur];
        #pragma unroll
        for (int j = 0; j < 4; j++) {            // 16-key slabs
            uint32_t b0[4], b1[4];
            int nrow = j * 16 + (lane & 7) + ((lane >> 4) << 3);
            ldmx4(b0[0], b0[1], b0[2], b0[3],
                  kba + (uint32_t)(nrow * PITCH + (lane & 8)) * 2);
            ldmx4(b1[0], b1[1], b1[2], b1[3],
                  kba + (uint32_t)(nrow * PITCH + 16 + (lane & 8)) * 2);

            float c[2][2][4];
            #pragma unroll
            for (int mt = 0; mt < 2; mt++) {
                #pragma unroll
                for (int i = 0; i < 4; i++) { c[mt][0][i] = 0.f; c[mt][1][i] = 0.f; }
                mma16816(c[mt][0], qa[mt][0], &b0[0]);
                mma16816(c[mt][0], qa[mt][1], &b1[0]);
                mma16816(c[mt][1], qa[mt][0], &b0[2]);
                mma16816(c[mt][1], qa[mt][1], &b1[2]);
            }

            // P = 2^score; one MUFU per 2 scores
            uint32_t pa[2][4];
            #pragma unroll
            for (int mt = 0; mt < 2; mt++) {
                pa[mt][0] = exp2h2(c[mt][0][0], c[mt][0][1]);
                pa[mt][1] = exp2h2(c[mt][0][2], c[mt][0][3]);
                pa[mt][2] = exp2h2(c[mt][1][0], c[mt][1][1]);
                pa[mt][3] = exp2h2(c[mt][1][2], c[mt][1][3]);
                mma16816h(Oext[mt], pa[mt], onesh);
            }

            int vrow = j * 16 + (lane & 15);
            uint32_t v0[4], v1[4];
            ldmx4t(v0[0], v0[1], v0[2], v0[3],
                   vba + (uint32_t)(vrow * PITCH + ((lane >> 4) << 3)) * 2);
            ldmx4t(v1[0], v1[1], v1[2], v1[3],
                   vba + (uint32_t)(vrow * PITCH + 16 + ((lane >> 4) << 3)) * 2);

            #pragma unroll
            for (int mt = 0; mt < 2; mt++) {
                mma16816h(O[mt][0], pa[mt], &v0[0]);
                mma16816h(O[mt][1], pa[mt], &v0[2]);
                mma16816h(O[mt][2], pa[mt], &v1[0]);
                mma16816h(O[mt][3], pa[mt], &v1[2]);
            }
        }
    }

    // epilogue: write UNNORMALIZED partial O (fp16 half2) + partial l
    int b = bh >> 3, h = bh & 7;
    __half* poz = po + (size_t)z * NTOK * DD;
    float*  plz = pl + (size_t)z * NTOK * HH;
    #pragma unroll
    for (int mt = 0; mt < 2; mt++) {
        int r0 = qt * 128 + w * 32 + mt * 16 + (lane >> 2);
        int n  = b * SS + r0;
        size_t base = (size_t)n * DD + h * DHH;
        if ((lane & 3) == 0) {
            plz[(size_t)n * HH + h]       = Oext[mt][0];
            plz[(size_t)(n + 8) * HH + h] = Oext[mt][2];
        }
        #pragma unroll
        for (int nt = 0; nt < 4; nt++) {
            int colo = nt * 8 + 2 * (lane & 3);
            *(__half2*)&poz[base + colo] =
                __floats2half2_rn(O[mt][nt][0], O[mt][nt][1]);
            *(__half2*)&poz[base + 8 * DD + colo] =
                __floats2half2_rn(O[mt][nt][2], O[mt][nt][3]);
        }
    }
}

// ---------------------------------------------------------------------------
// Split-K combine: ctx = (O0 + O1) / (l0 + l1), packed bf16. Pure streaming.
// One thread handles 8 consecutive elements; each partial read is one uint4.
// ---------------------------------------------------------------------------
__global__ __launch_bounds__(256) void attn_combine(const __half* __restrict__ po,
                                                    const float* __restrict__ pl,
                                                    __nv_bfloat16* __restrict__ ctx) {
    int i = blockIdx.x * 256 + threadIdx.x;    // 0 .. NTOK*DD/8 - 1
    size_t e = (size_t)i * 8;
    int n = (int)(e >> 8);                     // token
    int col = (int)(e & 255);
    int h = col >> 5;

    float l = pl[(size_t)n * HH + h] + pl[(size_t)NTOK * HH + (size_t)n * HH + h];
    float inv = 1.0f / l;

    uint4 pa = *(const uint4*)&po[e];                        // 8 halves, split 0
    uint4 pb = *(const uint4*)&po[(size_t)NTOK * DD + e];    // 8 halves, split 1

    const __half2* ha = reinterpret_cast<const __half2*>(&pa);
    const __half2* hb = reinterpret_cast<const __half2*>(&pb);

    uint4 pk;
    uint32_t* pko = reinterpret_cast<uint32_t*>(&pk);
    #pragma unroll
    for (int q = 0; q < 4; q++) {
        float2 fa = __half22float2(ha[q]);
        float2 fb = __half22float2(hb[q]);
        pko[q] = packbf((fa.x + fb.x) * inv, (fa.y + fb.y) * inv);
    }
    *(uint4*)&ctx[e] = pk;
}

// ---------------------------------------------------------------------------
// Launch
// ---------------------------------------------------------------------------
extern "C" void kernel_launch(void* const* d_in, const int* in_sizes, int n_in,
                              void* d_out, int out_size) {
    const float* x      = (const float*)d_in[0];
    const float* ln1_g  = (const float*)d_in[1];
    const float* ln1_b  = (const float*)d_in[2];
    const float* w_qkv  = (const float*)d_in[3];
    const float* b_qkv  = (const float*)d_in[4];
    const float* w_proj = (const float*)d_in[5];
    const float* b_proj = (const float*)d_in[6];
    const float* ln2_g  = (const float*)d_in[7];
    const float* ln2_b  = (const float*)d_in[8];
    const float* w1     = (const float*)d_in[9];
    const float* b1     = (const float*)d_in[10];
    const float* w2     = (const float*)d_in[11];
    const float* b2     = (const float*)d_in[12];
    float* out = (float*)d_out;

    __nv_bfloat16 *yb, *ctxb, *hb, *qb, *kb, *wqkvb, *wprojb, *w1b, *w2b;
    __half *vh, *po;
    float *x1, *pl;
    cudaGetSymbolAddress((void**)&yb,     g_yb);
    cudaGetSymbolAddress((void**)&ctxb,   g_ctxb);
    cudaGetSymbolAddress((void**)&x1,     g_x1);
    cudaGetSymbolAddress((void**)&hb,     g_hb);
    cudaGetSymbolAddress((void**)&qb,     g_qb);
    cudaGetSymbolAddress((void**)&kb,     g_kb);
    cudaGetSymbolAddress((void**)&vh,     g_vh);
    cudaGetSymbolAddress((void**)&wqkvb,  g_wqkvb);
    cudaGetSymbolAddress((void**)&wprojb, g_wprojb);
    cudaGetSymbolAddress((void**)&w1b,    g_w1b);
    cudaGetSymbolAddress((void**)&w2b,    g_w2b);
    cudaGetSymbolAddress((void**)&po,     g_po);
    cudaGetSymbolAddress((void**)&pl,     g_pl);

    // 0+1. fused weight conversion + LN1 (one launch)
    f2bf_ln<<<128 + NTOK/8, 256>>>(w_qkv, w_proj, w1, w2,
                                   wqkvb, wprojb, w1b, w2b,
                                   x, ln1_g, ln1_b, yb);
    // 2. QKV GEMM -> Q bf16 (pre-scaled) / K bf16 / V fp16
    gemm_bf<3><<<dim3(768/64, NTOK/128), 256>>>(yb, wqkvb, b_qkv, nullptr, nullptr,
                                                qb, kb, vh, 3*DD, DD);
    // 3. split-K attention -> fp16 partial O + fp32 l, then streaming combine
    attn_mma<<<dim3(BB*HH, SS/128, KSPLIT), 128>>>(qb, kb, vh, po, pl);
    attn_combine<<<NTOK*DD/8/256, 256>>>(po, pl, ctxb);
    // 4. proj + residual -> x1 fp32 (plain GEMM)
    gemm_bf<1><<<dim3(DD/64, NTOK/128), 256>>>(ctxb, wprojb, b_proj, x, x1,
                                               nullptr, nullptr, nullptr, DD, DD);
    // 5. LN2 -> bf16
    ln_kernel<<<NTOK/8, 256>>>(x1, ln2_g, ln2_b, yb);
    // 6. FFN1 + silu -> bf16 h
    gemm_bf<2><<<dim3(DFF/64, NTOK/128), 256>>>(yb, w1b, b1, nullptr, nullptr,
                                                hb, nullptr, nullptr, DFF, DD);
    // 7. FFN2 + residual -> out fp32
    gemm_bf<1><<<dim3(DD/64, NTOK/128), 256>>>(hb, w2b, b2, x1, out,
                                               nullptr, nullptr, nullptr, DD, DFF);
}